// round 11
// baseline (speedup 1.0000x reference)
#include <cuda_runtime.h>
#include <cuda_bf16.h>
#include <math.h>

// ---------------------------------------------------------------------------
// InternVisionLayer: B=16, S=1025, H=1024, NH=16, HD=64, I=4096, M = 16400
// R10: QKV/fc1 -> 128x256 CTA tile (warp 64x64): 4 MMA per ldmatrix, +33%
//      MACs/byte, half the barriers per FLOP. proj/fc2 + flash unchanged (R9).
// ---------------------------------------------------------------------------

#define M_TOK   16400
#define SEQ     1025
#define BATCH   16
#define HID     1024
#define NHEADS  16
#define HDIM    64
#define IMED    4096

__device__ __nv_bfloat16 g_xnorm [(size_t)M_TOK * HID];
__device__ __nv_bfloat16 g_qkv   [(size_t)M_TOK * 3 * HID];
__device__ __nv_bfloat16 g_attn  [(size_t)M_TOK * HID];
__device__ __nv_bfloat16 g_mlp   [(size_t)M_TOK * IMED];
__device__ __nv_bfloat16 g_qkvw  [(size_t)3 * HID * HID];
__device__ __nv_bfloat16 g_projw [(size_t)HID * HID];
__device__ __nv_bfloat16 g_fc1w  [(size_t)IMED * HID];
__device__ __nv_bfloat16 g_fc2w  [(size_t)HID * IMED];

// ---------------------------------------------------------------------------
// helpers
// ---------------------------------------------------------------------------
__device__ __forceinline__ void mma_bf16(float* d, const unsigned* a, const unsigned* b) {
    asm volatile(
        "mma.sync.aligned.m16n8k16.row.col.f32.bf16.bf16.f32 "
        "{%0,%1,%2,%3}, {%4,%5,%6,%7}, {%8,%9}, {%0,%1,%2,%3};"
        : "+f"(d[0]), "+f"(d[1]), "+f"(d[2]), "+f"(d[3])
        : "r"(a[0]), "r"(a[1]), "r"(a[2]), "r"(a[3]), "r"(b[0]), "r"(b[1]));
}

__device__ __forceinline__ void ldm_x4(unsigned& r0, unsigned& r1, unsigned& r2,
                                       unsigned& r3, unsigned saddr) {
    asm volatile("ldmatrix.sync.aligned.m8n8.x4.shared.b16 {%0,%1,%2,%3}, [%4];"
                 : "=r"(r0), "=r"(r1), "=r"(r2), "=r"(r3) : "r"(saddr));
}
__device__ __forceinline__ void ldm_x4t(unsigned& r0, unsigned& r1, unsigned& r2,
                                        unsigned& r3, unsigned saddr) {
    asm volatile("ldmatrix.sync.aligned.m8n8.x4.trans.shared.b16 {%0,%1,%2,%3}, [%4];"
                 : "=r"(r0), "=r"(r1), "=r"(r2), "=r"(r3) : "r"(saddr));
}

__device__ __forceinline__ void cp16s(unsigned sa, const void* gsrc) {
    asm volatile("cp.async.cg.shared.global [%0], [%1], 16;\n"
                 :: "r"(sa), "l"(gsrc));
}
__device__ __forceinline__ void cp_commit() { asm volatile("cp.async.commit_group;"); }

__device__ __forceinline__ float gelu_f(float v) {
    return 0.5f * v * (1.0f + erff(v * 0.70710678118654752f));
}

__device__ __forceinline__ unsigned packbf2(float lo, float hi) {
    __nv_bfloat162 p = __floats2bfloat162_rn(lo, hi);
    return *(unsigned*)&p;
}

__device__ __forceinline__ unsigned swz64(int r, int c) {
    return (unsigned)(r * 64 + (((c ^ (r >> 1)) & 3) << 4));
}
__device__ __forceinline__ unsigned swz128(int r, int c) {
    return (unsigned)(r * 128 + (((c ^ r) & 7) << 4));
}

// ---------------------------------------------------------------------------
// fp32 -> bf16 converter (weights)
// ---------------------------------------------------------------------------
__global__ void f2bf_k(const float* __restrict__ in, __nv_bfloat16* __restrict__ out,
                       int n4) {
    int i = blockIdx.x * blockDim.x + threadIdx.x;
    if (i < n4) {
        float4 v = ((const float4*)in)[i];
        ((__nv_bfloat162*)out)[2 * i + 0] = __floats2bfloat162_rn(v.x, v.y);
        ((__nv_bfloat162*)out)[2 * i + 1] = __floats2bfloat162_rn(v.z, v.w);
    }
}

// ---------------------------------------------------------------------------
// LayerNorm: one block (256 threads) per row of 1024; bf16 output
// ---------------------------------------------------------------------------
__global__ void layernorm_k(const float* __restrict__ x,
                            const float* __restrict__ g,
                            const float* __restrict__ b,
                            __nv_bfloat16* __restrict__ out) {
    int row = blockIdx.x;
    int t = threadIdx.x;
    const float4* xr = (const float4*)(x + (size_t)row * HID);
    float4 v = xr[t];
    float s  = v.x + v.y + v.z + v.w;
    float ss = v.x*v.x + v.y*v.y + v.z*v.z + v.w*v.w;
    #pragma unroll
    for (int o = 16; o; o >>= 1) {
        s  += __shfl_xor_sync(0xffffffffu, s,  o);
        ss += __shfl_xor_sync(0xffffffffu, ss, o);
    }
    __shared__ float sh[16];
    if ((t & 31) == 0) { sh[t >> 5] = s; sh[8 + (t >> 5)] = ss; }
    __syncthreads();
    s = 0.f; ss = 0.f;
    #pragma unroll
    for (int i = 0; i < 8; i++) { s += sh[i]; ss += sh[8 + i]; }
    float mean = s * (1.0f / HID);
    float var  = ss * (1.0f / HID) - mean * mean;
    float inv  = rsqrtf(var + 1e-5f);
    float4 gv = ((const float4*)g)[t];
    float4 bv = ((const float4*)b)[t];
    __nv_bfloat162* orow = (__nv_bfloat162*)(out + (size_t)row * HID);
    orow[2 * t + 0] = __floats2bfloat162_rn((v.x - mean) * inv * gv.x + bv.x,
                                            (v.y - mean) * inv * gv.y + bv.y);
    orow[2 * t + 1] = __floats2bfloat162_rn((v.z - mean) * inv * gv.z + bv.z,
                                            (v.w - mean) * inv * gv.w + bv.w);
}

// ---------------------------------------------------------------------------
// 128x128 bf16 GEMM (proven R9 kernel) — used for proj / fc2 (MODE 3).
// ---------------------------------------------------------------------------
#define GSM_BYTES (3 * 16384)

template <int MODE>
__global__ void __launch_bounds__(256, 2)
gemm_bf16(const __nv_bfloat16* __restrict__ A, const __nv_bfloat16* __restrict__ Bw,
          const float* __restrict__ bias, const float* __restrict__ ls,
          const float* __restrict__ resid, float* __restrict__ Cf,
          __nv_bfloat16* __restrict__ Cb, int M, int N, int K) {
    extern __shared__ __align__(128) char smx[];

    const int t  = threadIdx.x;
    const int w  = t >> 5;
    const int lane = t & 31;
    const int g  = lane >> 2;
    const int t4 = lane & 3;
    const int wm = (w >> 2) * 64;
    const int wn = (w & 3) * 32;
    const int m0 = blockIdx.y * 128;
    const int n0 = blockIdx.x * 128;

    const unsigned smb = (unsigned)__cvta_generic_to_shared(smx);

    float d[4][4][4];
    #pragma unroll
    for (int i = 0; i < 4; i++)
        #pragma unroll
        for (int j = 0; j < 4; j++)
            #pragma unroll
            for (int r = 0; r < 4; r++) d[i][j][r] = 0.f;

    const int r0 = t >> 2;
    const int c  = t & 3;
    const __nv_bfloat16* gA0 = A  + (size_t)min(m0 + r0,      M - 1) * K + c * 8;
    const __nv_bfloat16* gA1 = A  + (size_t)min(m0 + r0 + 64, M - 1) * K + c * 8;
    const __nv_bfloat16* gB0 = Bw + (size_t)(n0 + r0)      * K + c * 8;
    const __nv_bfloat16* gB1 = Bw + (size_t)(n0 + r0 + 64) * K + c * 8;

    auto stage = [&](int sg, int k0) {
        unsigned ab = smb + sg * 16384;
        cp16s(ab        + swz64(r0,      c), gA0 + k0);
        cp16s(ab        + swz64(r0 + 64, c), gA1 + k0);
        cp16s(ab + 8192 + swz64(r0,      c), gB0 + k0);
        cp16s(ab + 8192 + swz64(r0 + 64, c), gB1 + k0);
    };

    const int a_row = (lane & 15);
    const int a_c   = (lane >> 4);
    const int b_row = ((lane >> 4) << 3) + (lane & 7);
    const int b_c   = ((lane >> 3) & 1);

    const int NC = K >> 5;
    stage(0, 0);  cp_commit();
    stage(1, 32); cp_commit();

    int cs = 0, ss = 2;
    for (int kc = 0; kc < NC; kc++) {
        asm volatile("cp.async.wait_group 1;");
        __syncthreads();

        if (kc + 2 < NC) stage(ss, (kc + 2) << 5);
        cp_commit();

        const unsigned ab = smb + cs * 16384;
        const unsigned bb = ab + 8192;
        #pragma unroll
        for (int s = 0; s < 2; s++) {
            unsigned af[4][4], bf[2][4];
            #pragma unroll
            for (int i = 0; i < 4; i++)
                ldm_x4(af[i][0], af[i][1], af[i][2], af[i][3],
                       ab + swz64(wm + i * 16 + a_row, 2 * s + a_c));
            #pragma unroll
            for (int jj = 0; jj < 2; jj++)
                ldm_x4(bf[jj][0], bf[jj][1], bf[jj][2], bf[jj][3],
                       bb + swz64(wn + jj * 16 + b_row, 2 * s + b_c));
            #pragma unroll
            for (int i = 0; i < 4; i++)
                #pragma unroll
                for (int j = 0; j < 4; j++)
                    mma_bf16(d[i][j], af[i], &bf[j >> 1][(j & 1) * 2]);
        }
        cs = (cs == 2) ? 0 : cs + 1;
        ss = (ss == 2) ? 0 : ss + 1;
    }

    #pragma unroll
    for (int i = 0; i < 4; i++) {
        int rbase = m0 + wm + i * 16 + g;
        #pragma unroll
        for (int rr = 0; rr < 2; rr++) {
            int row = rbase + 8 * rr;
            if (row >= M) continue;
            #pragma unroll
            for (int j = 0; j < 4; j++) {
                int col = n0 + wn + j * 8 + 2 * t4;
                float v0 = d[i][j][rr * 2 + 0];
                float v1 = d[i][j][rr * 2 + 1];
                size_t idx = (size_t)row * N + col;
                if (MODE == 1) {
                    v0 += bias[col]; v1 += bias[col + 1];
                    *(__nv_bfloat162*)(Cb + idx) = __floats2bfloat162_rn(v0, v1);
                } else if (MODE == 2) {
                    v0 = gelu_f(v0 + bias[col]);
                    v1 = gelu_f(v1 + bias[col + 1]);
                    *(__nv_bfloat162*)(Cb + idx) = __floats2bfloat162_rn(v0, v1);
                } else {
                    float2 rv = *(const float2*)(resid + idx);
                    v0 = rv.x + ls[col]     * (v0 + bias[col]);
                    v1 = rv.y + ls[col + 1] * (v1 + bias[col + 1]);
                    *(float2*)(Cf + idx) = make_float2(v0, v1);
                }
            }
        }
    }
}

// ---------------------------------------------------------------------------
// 128x256 bf16 GEMM (wide) — warp tile 64x64; 4 MMA per ldmatrix.x4.
// Used for QKV (MODE 1) and fc1 (MODE 2); N must be a multiple of 256.
// smem: 3 stages x (A 8KB + B 16KB) = 72KB dynamic; 1 CTA/SM (regs).
// ---------------------------------------------------------------------------
#define WSM_STAGE 24576
#define WSM_BYTES (3 * WSM_STAGE)

template <int MODE>
__global__ void __launch_bounds__(256)
gemm_bf16_wide(const __nv_bfloat16* __restrict__ A, const __nv_bfloat16* __restrict__ Bw,
               const float* __restrict__ bias, __nv_bfloat16* __restrict__ Cb,
               int M, int N, int K) {
    extern __shared__ __align__(128) char smx[];

    const int t  = threadIdx.x;
    const int w  = t >> 5;
    const int lane = t & 31;
    const int g  = lane >> 2;
    const int t4 = lane & 3;
    const int wm = (w >> 2) * 64;
    const int wn = (w & 3) * 64;
    const int m0 = blockIdx.y * 128;
    const int n0 = blockIdx.x * 256;

    const unsigned smb = (unsigned)__cvta_generic_to_shared(smx);

    float d[4][8][4];
    #pragma unroll
    for (int i = 0; i < 4; i++)
        #pragma unroll
        for (int j = 0; j < 8; j++)
            #pragma unroll
            for (int r = 0; r < 4; r++) d[i][j][r] = 0.f;

    const int r0 = t >> 2;          // 0..63
    const int c  = t & 3;           // 16B chunk
    const __nv_bfloat16* gA0 = A  + (size_t)min(m0 + r0,      M - 1) * K + c * 8;
    const __nv_bfloat16* gA1 = A  + (size_t)min(m0 + r0 + 64, M - 1) * K + c * 8;
    const __nv_bfloat16* gB0 = Bw + (size_t)(n0 + r0)       * K + c * 8;
    const __nv_bfloat16* gB1 = Bw + (size_t)(n0 + r0 + 64)  * K + c * 8;
    const __nv_bfloat16* gB2 = Bw + (size_t)(n0 + r0 + 128) * K + c * 8;
    const __nv_bfloat16* gB3 = Bw + (size_t)(n0 + r0 + 192) * K + c * 8;

    auto stage = [&](int sg, int k0) {
        unsigned ab = smb + sg * WSM_STAGE;
        unsigned bb = ab + 8192;
        cp16s(ab + swz64(r0,      c), gA0 + k0);
        cp16s(ab + swz64(r0 + 64, c), gA1 + k0);
        cp16s(bb + swz64(r0,       c), gB0 + k0);
        cp16s(bb + swz64(r0 + 64,  c), gB1 + k0);
        cp16s(bb + swz64(r0 + 128, c), gB2 + k0);
        cp16s(bb + swz64(r0 + 192, c), gB3 + k0);
    };

    const int a_row = (lane & 15);
    const int a_c   = (lane >> 4);
    const int b_row = ((lane >> 4) << 3) + (lane & 7);
    const int b_c   = ((lane >> 3) & 1);

    const int NC = K >> 5;
    stage(0, 0);  cp_commit();
    stage(1, 32); cp_commit();

    int cs = 0, ss = 2;
    for (int kc = 0; kc < NC; kc++) {
        asm volatile("cp.async.wait_group 1;");
        __syncthreads();

        if (kc + 2 < NC) stage(ss, (kc + 2) << 5);
        cp_commit();

        const unsigned ab = smb + cs * WSM_STAGE;
        const unsigned bb = ab + 8192;
        #pragma unroll
        for (int s = 0; s < 2; s++) {
            unsigned af[4][4], bf[4][4];
            #pragma unroll
            for (int i = 0; i < 4; i++)
                ldm_x4(af[i][0], af[i][1], af[i][2], af[i][3],
                       ab + swz64(wm + i * 16 + a_row, 2 * s + a_c));
            #pragma unroll
            for (int jj = 0; jj < 4; jj++)
                ldm_x4(bf[jj][0], bf[jj][1], bf[jj][2], bf[jj][3],
                       bb + swz64(wn + jj * 16 + b_row, 2 * s + b_c));
            #pragma unroll
            for (int i = 0; i < 4; i++)
                #pragma unroll
                for (int j = 0; j < 8; j++)
                    mma_bf16(d[i][j], af[i], &bf[j >> 1][(j & 1) * 2]);
        }
        cs = (cs == 2) ? 0 : cs + 1;
        ss = (ss == 2) ? 0 : ss + 1;
    }

    #pragma unroll
    for (int i = 0; i < 4; i++) {
        int rbase = m0 + wm + i * 16 + g;
        #pragma unroll
        for (int rr = 0; rr < 2; rr++) {
            int row = rbase + 8 * rr;
            if (row >= M) continue;
            #pragma unroll
            for (int j = 0; j < 8; j++) {
                int col = n0 + wn + j * 8 + 2 * t4;
                float v0 = d[i][j][rr * 2 + 0];
                float v1 = d[i][j][rr * 2 + 1];
                size_t idx = (size_t)row * N + col;
                if (MODE == 2) {
                    v0 = gelu_f(v0 + bias[col]);
                    v1 = gelu_f(v1 + bias[col + 1]);
                } else {
                    v0 += bias[col]; v1 += bias[col + 1];
                }
                *(__nv_bfloat162*)(Cb + idx) = __floats2bfloat162_rn(v0, v1);
            }
        }
    }
}

// ---------------------------------------------------------------------------
// bf16 flash attention (identical to R8/R9). CTA = (q-tile 128, b*h).
// ---------------------------------------------------------------------------
#define NIT 17

__global__ void __launch_bounds__(256, 1)
flash_attn(const __nv_bfloat16* __restrict__ qkv, __nv_bfloat16* __restrict__ out) {
    __shared__ __align__(128) char sm[49152];
    const unsigned smb = (unsigned)__cvta_generic_to_shared(sm);
    const unsigned smK = smb + 16384;
    const unsigned smV = smb + 32768;

    const int t  = threadIdx.x;
    const int w  = t >> 5;
    const int lane = t & 31;
    const int g  = lane >> 2;
    const int t4 = lane & 3;
    const int q0 = blockIdx.x * 128;
    const int z  = blockIdx.y, b = z >> 4, h = z & 15;

    const __nv_bfloat16* Qg = qkv + (size_t)b * SEQ * (3 * HID) + h * HDIM;
    const __nv_bfloat16* Kg = Qg + HID;
    const __nv_bfloat16* Vg = Qg + 2 * HID;

    {
        #pragma unroll
        for (int i = 0; i < 4; i++) {
            int id = t + i * 256;
            int r = id >> 3, c = id & 7;
            int row = min(q0 + r, SEQ - 1);
            cp16s(smb + swz128(r, c), Qg + (size_t)row * (3 * HID) + c * 8);
        }
        #pragma unroll
        for (int i = 0; i < 2; i++) {
            int id = t + i * 256;
            int r = id >> 3, c = id & 7;
            cp16s(smK + swz128(r, c), Kg + (size_t)r * (3 * HID) + c * 8);
            cp16s(smV + swz128(r, c), Vg + (size_t)r * (3 * HID) + c * 8);
        }
        cp_commit();
        asm volatile("cp.async.wait_group 0;");
        __syncthreads();
    }

    unsigned qf[4][4];
    #pragma unroll
    for (int kc = 0; kc < 4; kc++)
        ldm_x4(qf[kc][0], qf[kc][1], qf[kc][2], qf[kc][3],
               smb + swz128(w * 16 + (lane & 15), kc * 2 + (lane >> 4)));

    float m0 = -1e30f, m1 = -1e30f, l0 = 0.f, l1 = 0.f;
    float o[8][4];
    #pragma unroll
    for (int j = 0; j < 8; j++)
        #pragma unroll
        for (int r = 0; r < 4; r++) o[j][r] = 0.f;

    const int nt_r = (lane & 7);
    const int nt_p = (lane >> 4);
    const int nt_k = ((lane >> 3) & 1);

    for (int it = 0; it < NIT; it++) {
        const int buf = it & 1;
        const int kv0 = it * 64;

        if (it + 1 < NIT) {
            int nb = buf ^ 1;
            #pragma unroll
            for (int i = 0; i < 2; i++) {
                int id = t + i * 256;
                int r = id >> 3, c = id & 7;
                int row = min(kv0 + 64 + r, SEQ - 1);
                cp16s(smK + nb * 8192 + swz128(r, c), Kg + (size_t)row * (3 * HID) + c * 8);
                cp16s(smV + nb * 8192 + swz128(r, c), Vg + (size_t)row * (3 * HID) + c * 8);
            }
            cp_commit();
        }

        const unsigned kb = smK + buf * 8192;
        float s[8][4];
        #pragma unroll
        for (int j = 0; j < 8; j++)
            #pragma unroll
            for (int r = 0; r < 4; r++) s[j][r] = 0.f;
        #pragma unroll
        for (int kc = 0; kc < 4; kc++) {
            #pragma unroll
            for (int jp = 0; jp < 4; jp++) {
                unsigned kf[4];
                ldm_x4(kf[0], kf[1], kf[2], kf[3],
                       kb + swz128((2 * jp + nt_p) * 8 + nt_r, kc * 2 + nt_k));
                mma_bf16(s[2 * jp],     qf[kc], kf);
                mma_bf16(s[2 * jp + 1], qf[kc], kf + 2);
            }
        }

        #pragma unroll
        for (int j = 0; j < 8; j++) {
            s[j][0] *= 0.125f; s[j][1] *= 0.125f;
            s[j][2] *= 0.125f; s[j][3] *= 0.125f;
        }
        const int lim = SEQ - kv0;
        if (lim < 64) {
            #pragma unroll
            for (int j = 0; j < 8; j++) {
                int cc = j * 8 + 2 * t4;
                if (cc     >= lim) { s[j][0] = -1e30f; s[j][2] = -1e30f; }
                if (cc + 1 >= lim) { s[j][1] = -1e30f; s[j][3] = -1e30f; }
            }
        }

        float mx0 = -1e30f, mx1 = -1e30f;
        #pragma unroll
        for (int j = 0; j < 8; j++) {
            mx0 = fmaxf(mx0, fmaxf(s[j][0], s[j][1]));
            mx1 = fmaxf(mx1, fmaxf(s[j][2], s[j][3]));
        }
        mx0 = fmaxf(mx0, __shfl_xor_sync(0xffffffffu, mx0, 1));
        mx0 = fmaxf(mx0, __shfl_xor_sync(0xffffffffu, mx0, 2));
        mx1 = fmaxf(mx1, __shfl_xor_sync(0xffffffffu, mx1, 1));
        mx1 = fmaxf(mx1, __shfl_xor_sync(0xffffffffu, mx1, 2));

        float mn0 = fmaxf(m0, mx0), mn1 = fmaxf(m1, mx1);
        float a0 = __expf(m0 - mn0), a1 = __expf(m1 - mn1);
        m0 = mn0; m1 = mn1;

        float rs0 = 0.f, rs1 = 0.f;
        #pragma unroll
        for (int j = 0; j < 8; j++) {
            s[j][0] = __expf(s[j][0] - m0);
            s[j][1] = __expf(s[j][1] - m0);
            s[j][2] = __expf(s[j][2] - m1);
            s[j][3] = __expf(s[j][3] - m1);
            rs0 += s[j][0] + s[j][1];
            rs1 += s[j][2] + s[j][3];
        }
        rs0 += __shfl_xor_sync(0xffffffffu, rs0, 1);
        rs0 += __shfl_xor_sync(0xffffffffu, rs0, 2);
        rs1 += __shfl_xor_sync(0xffffffffu, rs1, 1);
        rs1 += __shfl_xor_sync(0xffffffffu, rs1, 2);
        l0 = l0 * a0 + rs0;
        l1 = l1 * a1 + rs1;

        unsigned pa[4][4];
        #pragma unroll
        for (int kk = 0; kk < 4; kk++) {
            pa[kk][0] = packbf2(s[2 * kk][0],     s[2 * kk][1]);
            pa[kk][1] = packbf2(s[2 * kk][2],     s[2 * kk][3]);
            pa[kk][2] = packbf2(s[2 * kk + 1][0], s[2 * kk + 1][1]);
            pa[kk][3] = packbf2(s[2 * kk + 1][2], s[2 * kk + 1][3]);
        }

        #pragma unroll
        for (int j = 0; j < 8; j++) {
            o[j][0] *= a0; o[j][1] *= a0; o[j][2] *= a1; o[j][3] *= a1;
        }

        const unsigned vb = smV + buf * 8192;
        #pragma unroll
        for (int kk = 0; kk < 4; kk++) {
            #pragma unroll
            for (int jp = 0; jp < 4; jp++) {
                unsigned vf[4];
                ldm_x4t(vf[0], vf[1], vf[2], vf[3],
                        vb + swz128(kk * 16 + nt_k * 8 + nt_r, 2 * jp + nt_p));
                mma_bf16(o[2 * jp],     pa[kk], vf);
                mma_bf16(o[2 * jp + 1], pa[kk], vf + 2);
            }
        }

        if (it + 1 < NIT) {
            asm volatile("cp.async.wait_group 0;");
            __syncthreads();
        }
    }

    float inv0 = 1.f / l0, inv1 = 1.f / l1;
    int row0 = q0 + w * 16 + g;
    int row1 = row0 + 8;
    #pragma unroll
    for (int j = 0; j < 8; j++) {
        int col = j * 8 + 2 * t4;
        if (row0 < SEQ)
            *(__nv_bfloat162*)(out + ((size_t)b * SEQ + row0) * HID + h * HDIM + col) =
                __floats2bfloat162_rn(o[j][0] * inv0, o[j][1] * inv0);
        if (row1 < SEQ)
            *(__nv_bfloat162*)(out + ((size_t)b * SEQ + row1) * HID + h * HDIM + col) =
                __floats2bfloat162_rn(o[j][2] * inv1, o[j][3] * inv1);
    }
}

// ---------------------------------------------------------------------------
extern "C" void kernel_launch(void* const* d_in, const int* in_sizes, int n_in,
                              void* d_out, int out_size) {
    const float* hidden = (const float*)d_in[0];
    const float* n1g    = (const float*)d_in[1];
    const float* n1b    = (const float*)d_in[2];
    const float* qkvw   = (const float*)d_in[3];
    const float* qkvb   = (const float*)d_in[4];
    const float* projw  = (const float*)d_in[5];
    const float* projb  = (const float*)d_in[6];
    const float* ls1    = (const float*)d_in[7];
    const float* n2g    = (const float*)d_in[8];
    const float* n2b    = (const float*)d_in[9];
    const float* fc1w   = (const float*)d_in[10];
    const float* fc1b   = (const float*)d_in[11];
    const float* fc2w   = (const float*)d_in[12];
    const float* fc2b   = (const float*)d_in[13];
    const float* ls2    = (const float*)d_in[14];
    float* out = (float*)d_out;

    __nv_bfloat16 *xnorm, *qkv, *attn, *mlp, *qkvw_bf, *projw_bf, *fc1w_bf, *fc2w_bf;
    cudaGetSymbolAddress((void**)&xnorm,    g_xnorm);
    cudaGetSymbolAddress((void**)&qkv,      g_qkv);
    cudaGetSymbolAddress((void**)&attn,     g_attn);
    cudaGetSymbolAddress((void**)&mlp,      g_mlp);
    cudaGetSymbolAddress((void**)&qkvw_bf,  g_qkvw);
    cudaGetSymbolAddress((void**)&projw_bf, g_projw);
    cudaGetSymbolAddress((void**)&fc1w_bf,  g_fc1w);
    cudaGetSymbolAddress((void**)&fc2w_bf,  g_fc2w);

    cudaFuncSetAttribute(gemm_bf16<3>,      cudaFuncAttributeMaxDynamicSharedMemorySize, GSM_BYTES);
    cudaFuncSetAttribute(gemm_bf16_wide<1>, cudaFuncAttributeMaxDynamicSharedMemorySize, WSM_BYTES);
    cudaFuncSetAttribute(gemm_bf16_wide<2>, cudaFuncAttributeMaxDynamicSharedMemorySize, WSM_BYTES);

    const int MT = (M_TOK + 127) / 128;  // 129
    const int QT = (SEQ + 127) / 128;    // 9

    // 0. weight conversion fp32 -> bf16
    {
        int n;
        n = 3 * HID * HID / 4; f2bf_k<<<(n + 255) / 256, 256>>>(qkvw, qkvw_bf, n);
        n = HID * HID / 4;     f2bf_k<<<(n + 255) / 256, 256>>>(projw, projw_bf, n);
        n = IMED * HID / 4;    f2bf_k<<<(n + 255) / 256, 256>>>(fc1w, fc1w_bf, n);
        n = HID * IMED / 4;    f2bf_k<<<(n + 255) / 256, 256>>>(fc2w, fc2w_bf, n);
    }

    // 1. LN1 -> bf16
    layernorm_k<<<M_TOK, 256>>>(hidden, n1g, n1b, xnorm);
    // 2. QKV -> bf16 (wide tile)
    gemm_bf16_wide<1><<<dim3(3 * HID / 256, MT), 256, WSM_BYTES>>>(
        xnorm, qkvw_bf, qkvb, qkv, M_TOK, 3 * HID, HID);
    // 3-5. fused attention
    flash_attn<<<dim3(QT, BATCH * NHEADS), 256>>>(qkv, attn);
    // 6. proj + ls1 residual -> d_out (fp32)
    gemm_bf16<3><<<dim3(HID / 128, MT), 256, GSM_BYTES>>>(
        attn, projw_bf, projb, ls1, hidden, out, nullptr, M_TOK, HID, HID);
    // 7. LN2 -> bf16
    layernorm_k<<<M_TOK, 256>>>(out, n2g, n2b, xnorm);
    // 8. fc1 + gelu -> bf16 (wide tile)
    gemm_bf16_wide<2><<<dim3(IMED / 256, MT), 256, WSM_BYTES>>>(
        xnorm, fc1w_bf, fc1b, mlp, M_TOK, IMED, HID);
    // 9. fc2 + ls2 residual -> d_out (fp32, in place)
    gemm_bf16<3><<<dim3(HID / 128, MT), 256, GSM_BYTES>>>(
        mlp, fc2w_bf, fc2b, ls2, out, out, nullptr, M_TOK, HID, IMED);
}

// round 13
// speedup vs baseline: 1.1526x; 1.1526x over previous
#include <cuda_runtime.h>
#include <cuda_bf16.h>
#include <math.h>

// ---------------------------------------------------------------------------
// InternVisionLayer: B=16, S=1025, H=1024, NH=16, HD=64, I=4096, M = 16400
// R12: tcgen05 unavailable (harness PTX targets sm_103, not sm_103a) -> stay
//      on mma.sync. Dense GEMMs: K-chunk 32 -> 64 (128B rows, swz128),
//      3-stage ring, half the barriers per FLOP, still 2 CTAs/SM.
//      Flash + LN identical to R9 (1501us baseline).
// ---------------------------------------------------------------------------

#define M_TOK   16400
#define SEQ     1025
#define BATCH   16
#define HID     1024
#define NHEADS  16
#define HDIM    64
#define IMED    4096

__device__ __nv_bfloat16 g_xnorm [(size_t)M_TOK * HID];
__device__ __nv_bfloat16 g_qkv   [(size_t)M_TOK * 3 * HID];
__device__ __nv_bfloat16 g_attn  [(size_t)M_TOK * HID];
__device__ __nv_bfloat16 g_mlp   [(size_t)M_TOK * IMED];
__device__ __nv_bfloat16 g_qkvw  [(size_t)3 * HID * HID];
__device__ __nv_bfloat16 g_projw [(size_t)HID * HID];
__device__ __nv_bfloat16 g_fc1w  [(size_t)IMED * HID];
__device__ __nv_bfloat16 g_fc2w  [(size_t)HID * IMED];

// ---------------------------------------------------------------------------
// helpers
// ---------------------------------------------------------------------------
__device__ __forceinline__ void mma_bf16(float* d, const unsigned* a, const unsigned* b) {
    asm volatile(
        "mma.sync.aligned.m16n8k16.row.col.f32.bf16.bf16.f32 "
        "{%0,%1,%2,%3}, {%4,%5,%6,%7}, {%8,%9}, {%0,%1,%2,%3};"
        : "+f"(d[0]), "+f"(d[1]), "+f"(d[2]), "+f"(d[3])
        : "r"(a[0]), "r"(a[1]), "r"(a[2]), "r"(a[3]), "r"(b[0]), "r"(b[1]));
}

__device__ __forceinline__ void ldm_x4(unsigned& r0, unsigned& r1, unsigned& r2,
                                       unsigned& r3, unsigned saddr) {
    asm volatile("ldmatrix.sync.aligned.m8n8.x4.shared.b16 {%0,%1,%2,%3}, [%4];"
                 : "=r"(r0), "=r"(r1), "=r"(r2), "=r"(r3) : "r"(saddr));
}
__device__ __forceinline__ void ldm_x4t(unsigned& r0, unsigned& r1, unsigned& r2,
                                        unsigned& r3, unsigned saddr) {
    asm volatile("ldmatrix.sync.aligned.m8n8.x4.trans.shared.b16 {%0,%1,%2,%3}, [%4];"
                 : "=r"(r0), "=r"(r1), "=r"(r2), "=r"(r3) : "r"(saddr));
}

__device__ __forceinline__ void cp16s(unsigned sa, const void* gsrc) {
    asm volatile("cp.async.cg.shared.global [%0], [%1], 16;\n"
                 :: "r"(sa), "l"(gsrc));
}
__device__ __forceinline__ void cp_commit() { asm volatile("cp.async.commit_group;"); }

__device__ __forceinline__ float gelu_f(float v) {
    return 0.5f * v * (1.0f + erff(v * 0.70710678118654752f));
}

__device__ __forceinline__ unsigned packbf2(float lo, float hi) {
    __nv_bfloat162 p = __floats2bfloat162_rn(lo, hi);
    return *(unsigned*)&p;
}

// 128-byte rows, 8 x 16B chunks, XOR swizzle (conflict-free for ldmatrix)
__device__ __forceinline__ unsigned swz128(int r, int c) {
    return (unsigned)(r * 128 + (((c ^ r) & 7) << 4));
}

// ---------------------------------------------------------------------------
// fp32 -> bf16 converter (weights)
// ---------------------------------------------------------------------------
__global__ void f2bf_k(const float* __restrict__ in, __nv_bfloat16* __restrict__ out,
                       int n4) {
    int i = blockIdx.x * blockDim.x + threadIdx.x;
    if (i < n4) {
        float4 v = ((const float4*)in)[i];
        ((__nv_bfloat162*)out)[2 * i + 0] = __floats2bfloat162_rn(v.x, v.y);
        ((__nv_bfloat162*)out)[2 * i + 1] = __floats2bfloat162_rn(v.z, v.w);
    }
}

// ---------------------------------------------------------------------------
// LayerNorm: one block (256 threads) per row of 1024; bf16 output
// ---------------------------------------------------------------------------
__global__ void layernorm_k(const float* __restrict__ x,
                            const float* __restrict__ g,
                            const float* __restrict__ b,
                            __nv_bfloat16* __restrict__ out) {
    int row = blockIdx.x;
    int t = threadIdx.x;
    const float4* xr = (const float4*)(x + (size_t)row * HID);
    float4 v = xr[t];
    float s  = v.x + v.y + v.z + v.w;
    float ss = v.x*v.x + v.y*v.y + v.z*v.z + v.w*v.w;
    #pragma unroll
    for (int o = 16; o; o >>= 1) {
        s  += __shfl_xor_sync(0xffffffffu, s,  o);
        ss += __shfl_xor_sync(0xffffffffu, ss, o);
    }
    __shared__ float sh[16];
    if ((t & 31) == 0) { sh[t >> 5] = s; sh[8 + (t >> 5)] = ss; }
    __syncthreads();
    s = 0.f; ss = 0.f;
    #pragma unroll
    for (int i = 0; i < 8; i++) { s += sh[i]; ss += sh[8 + i]; }
    float mean = s * (1.0f / HID);
    float var  = ss * (1.0f / HID) - mean * mean;
    float inv  = rsqrtf(var + 1e-5f);
    float4 gv = ((const float4*)g)[t];
    float4 bv = ((const float4*)b)[t];
    __nv_bfloat162* orow = (__nv_bfloat162*)(out + (size_t)row * HID);
    orow[2 * t + 0] = __floats2bfloat162_rn((v.x - mean) * inv * gv.x + bv.x,
                                            (v.y - mean) * inv * gv.y + bv.y);
    orow[2 * t + 1] = __floats2bfloat162_rn((v.z - mean) * inv * gv.z + bv.z,
                                            (v.w - mean) * inv * gv.w + bv.w);
}

// ---------------------------------------------------------------------------
// bf16 MMA GEMM: C = A[M,K] * B[N,K]^T, CTA 128x128, 8 warps of 64x32.
// K-chunk 64 (128B rows, swz128), 3-stage cp.async ring (3x32KB), ONE
// barrier per chunk. 2 CTAs/SM.
// MODE 1: +bias -> bf16   MODE 2: +bias, gelu -> bf16
// MODE 3: resid + ls*( . + bias ) -> fp32
// ---------------------------------------------------------------------------
#define GSM_STAGE 32768
#define GSM_BYTES (3 * GSM_STAGE)

template <int MODE>
__global__ void __launch_bounds__(256, 2)
gemm_bf16(const __nv_bfloat16* __restrict__ A, const __nv_bfloat16* __restrict__ Bw,
          const float* __restrict__ bias, const float* __restrict__ ls,
          const float* __restrict__ resid, float* __restrict__ Cf,
          __nv_bfloat16* __restrict__ Cb, int M, int N, int K) {
    extern __shared__ __align__(128) char smx[];

    const int t  = threadIdx.x;
    const int w  = t >> 5;
    const int lane = t & 31;
    const int g  = lane >> 2;
    const int t4 = lane & 3;
    const int wm = (w >> 2) * 64;
    const int wn = (w & 3) * 32;
    const int m0 = blockIdx.y * 128;
    const int n0 = blockIdx.x * 128;

    const unsigned smb = (unsigned)__cvta_generic_to_shared(smx);

    float d[4][4][4];
    #pragma unroll
    for (int i = 0; i < 4; i++)
        #pragma unroll
        for (int j = 0; j < 4; j++)
            #pragma unroll
            for (int r = 0; r < 4; r++) d[i][j][r] = 0.f;

    // staging: 128 rows x 8 chunks per matrix; 4 (row,chunk) pairs per thread
    auto stage = [&](int sg, int k0) {
        unsigned ab = smb + sg * GSM_STAGE;
        unsigned bb = ab + 16384;
        #pragma unroll
        for (int i = 0; i < 4; i++) {
            int id = t + i * 256;
            int r = id >> 3, c = id & 7;
            int rm = min(m0 + r, M - 1);
            cp16s(ab + swz128(r, c), A  + (size_t)rm * K + k0 + c * 8);
            cp16s(bb + swz128(r, c), Bw + (size_t)(n0 + r) * K + k0 + c * 8);
        }
    };

    const int a_row = (lane & 15);
    const int a_c   = (lane >> 4);
    const int b_row = ((lane >> 4) << 3) + (lane & 7);
    const int b_c   = ((lane >> 3) & 1);

    const int NC = K >> 6;        // chunks of 64
    stage(0, 0);  cp_commit();
    stage(1, 64); cp_commit();

    int cs = 0, ss = 2;
    for (int kc = 0; kc < NC; kc++) {
        asm volatile("cp.async.wait_group 1;");
        __syncthreads();

        if (kc + 2 < NC) stage(ss, (kc + 2) << 6);
        cp_commit();

        const unsigned ab = smx ? smb + cs * GSM_STAGE : 0;
        const unsigned bb = ab + 16384;
        #pragma unroll
        for (int s = 0; s < 4; s++) {        // 4 x k16
            unsigned af[4][4], bf[2][4];
            #pragma unroll
            for (int i = 0; i < 4; i++)
                ldm_x4(af[i][0], af[i][1], af[i][2], af[i][3],
                       ab + swz128(wm + i * 16 + a_row, 2 * s + a_c));
            #pragma unroll
            for (int jj = 0; jj < 2; jj++)
                ldm_x4(bf[jj][0], bf[jj][1], bf[jj][2], bf[jj][3],
                       bb + swz128(wn + jj * 16 + b_row, 2 * s + b_c));
            #pragma unroll
            for (int i = 0; i < 4; i++)
                #pragma unroll
                for (int j = 0; j < 4; j++)
                    mma_bf16(d[i][j], af[i], &bf[j >> 1][(j & 1) * 2]);
        }
        cs = (cs == 2) ? 0 : cs + 1;
        ss = (ss == 2) ? 0 : ss + 1;
    }

    #pragma unroll
    for (int i = 0; i < 4; i++) {
        int rbase = m0 + wm + i * 16 + g;
        #pragma unroll
        for (int rr = 0; rr < 2; rr++) {
            int row = rbase + 8 * rr;
            if (row >= M) continue;
            #pragma unroll
            for (int j = 0; j < 4; j++) {
                int col = n0 + wn + j * 8 + 2 * t4;
                float v0 = d[i][j][rr * 2 + 0];
                float v1 = d[i][j][rr * 2 + 1];
                size_t idx = (size_t)row * N + col;
                if (MODE == 1) {
                    v0 += bias[col]; v1 += bias[col + 1];
                    *(__nv_bfloat162*)(Cb + idx) = __floats2bfloat162_rn(v0, v1);
                } else if (MODE == 2) {
                    v0 = gelu_f(v0 + bias[col]);
                    v1 = gelu_f(v1 + bias[col + 1]);
                    *(__nv_bfloat162*)(Cb + idx) = __floats2bfloat162_rn(v0, v1);
                } else {
                    float2 rv = *(const float2*)(resid + idx);
                    v0 = rv.x + ls[col]     * (v0 + bias[col]);
                    v1 = rv.y + ls[col + 1] * (v1 + bias[col + 1]);
                    *(float2*)(Cf + idx) = make_float2(v0, v1);
                }
            }
        }
    }
}

// ---------------------------------------------------------------------------
// bf16 flash attention (identical to R9). CTA = (q-tile 128, b*h).
// ---------------------------------------------------------------------------
#define NIT 17

__global__ void __launch_bounds__(256, 1)
flash_attn(const __nv_bfloat16* __restrict__ qkv, __nv_bfloat16* __restrict__ out) {
    __shared__ __align__(128) char sm[49152];
    const unsigned smb = (unsigned)__cvta_generic_to_shared(sm);
    const unsigned smK = smb + 16384;
    const unsigned smV = smb + 32768;

    const int t  = threadIdx.x;
    const int w  = t >> 5;
    const int lane = t & 31;
    const int g  = lane >> 2;
    const int t4 = lane & 3;
    const int q0 = blockIdx.x * 128;
    const int z  = blockIdx.y, b = z >> 4, h = z & 15;

    const __nv_bfloat16* Qg = qkv + (size_t)b * SEQ * (3 * HID) + h * HDIM;
    const __nv_bfloat16* Kg = Qg + HID;
    const __nv_bfloat16* Vg = Qg + 2 * HID;

    {
        #pragma unroll
        for (int i = 0; i < 4; i++) {
            int id = t + i * 256;
            int r = id >> 3, c = id & 7;
            int row = min(q0 + r, SEQ - 1);
            cp16s(smb + swz128(r, c), Qg + (size_t)row * (3 * HID) + c * 8);
        }
        #pragma unroll
        for (int i = 0; i < 2; i++) {
            int id = t + i * 256;
            int r = id >> 3, c = id & 7;
            cp16s(smK + swz128(r, c), Kg + (size_t)r * (3 * HID) + c * 8);
            cp16s(smV + swz128(r, c), Vg + (size_t)r * (3 * HID) + c * 8);
        }
        cp_commit();
        asm volatile("cp.async.wait_group 0;");
        __syncthreads();
    }

    unsigned qf[4][4];
    #pragma unroll
    for (int kc = 0; kc < 4; kc++)
        ldm_x4(qf[kc][0], qf[kc][1], qf[kc][2], qf[kc][3],
               smb + swz128(w * 16 + (lane & 15), kc * 2 + (lane >> 4)));

    float m0 = -1e30f, m1 = -1e30f, l0 = 0.f, l1 = 0.f;
    float o[8][4];
    #pragma unroll
    for (int j = 0; j < 8; j++)
        #pragma unroll
        for (int r = 0; r < 4; r++) o[j][r] = 0.f;

    const int nt_r = (lane & 7);
    const int nt_p = (lane >> 4);
    const int nt_k = ((lane >> 3) & 1);

    for (int it = 0; it < NIT; it++) {
        const int buf = it & 1;
        const int kv0 = it * 64;

        if (it + 1 < NIT) {
            int nb = buf ^ 1;
            #pragma unroll
            for (int i = 0; i < 2; i++) {
                int id = t + i * 256;
                int r = id >> 3, c = id & 7;
                int row = min(kv0 + 64 + r, SEQ - 1);
                cp16s(smK + nb * 8192 + swz128(r, c), Kg + (size_t)row * (3 * HID) + c * 8);
                cp16s(smV + nb * 8192 + swz128(r, c), Vg + (size_t)row * (3 * HID) + c * 8);
            }
            cp_commit();
        }

        const unsigned kb = smK + buf * 8192;
        float s[8][4];
        #pragma unroll
        for (int j = 0; j < 8; j++)
            #pragma unroll
            for (int r = 0; r < 4; r++) s[j][r] = 0.f;
        #pragma unroll
        for (int kc = 0; kc < 4; kc++) {
            #pragma unroll
            for (int jp = 0; jp < 4; jp++) {
                unsigned kf[4];
                ldm_x4(kf[0], kf[1], kf[2], kf[3],
                       kb + swz128((2 * jp + nt_p) * 8 + nt_r, kc * 2 + nt_k));
                mma_bf16(s[2 * jp],     qf[kc], kf);
                mma_bf16(s[2 * jp + 1], qf[kc], kf + 2);
            }
        }

        #pragma unroll
        for (int j = 0; j < 8; j++) {
            s[j][0] *= 0.125f; s[j][1] *= 0.125f;
            s[j][2] *= 0.125f; s[j][3] *= 0.125f;
        }
        const int lim = SEQ - kv0;
        if (lim < 64) {
            #pragma unroll
            for (int j = 0; j < 8; j++) {
                int cc = j * 8 + 2 * t4;
                if (cc     >= lim) { s[j][0] = -1e30f; s[j][2] = -1e30f; }
                if (cc + 1 >= lim) { s[j][1] = -1e30f; s[j][3] = -1e30f; }
            }
        }

        float mx0 = -1e30f, mx1 = -1e30f;
        #pragma unroll
        for (int j = 0; j < 8; j++) {
            mx0 = fmaxf(mx0, fmaxf(s[j][0], s[j][1]));
            mx1 = fmaxf(mx1, fmaxf(s[j][2], s[j][3]));
        }
        mx0 = fmaxf(mx0, __shfl_xor_sync(0xffffffffu, mx0, 1));
        mx0 = fmaxf(mx0, __shfl_xor_sync(0xffffffffu, mx0, 2));
        mx1 = fmaxf(mx1, __shfl_xor_sync(0xffffffffu, mx1, 1));
        mx1 = fmaxf(mx1, __shfl_xor_sync(0xffffffffu, mx1, 2));

        float mn0 = fmaxf(m0, mx0), mn1 = fmaxf(m1, mx1);
        float a0 = __expf(m0 - mn0), a1 = __expf(m1 - mn1);
        m0 = mn0; m1 = mn1;

        float rs0 = 0.f, rs1 = 0.f;
        #pragma unroll
        for (int j = 0; j < 8; j++) {
            s[j][0] = __expf(s[j][0] - m0);
            s[j][1] = __expf(s[j][1] - m0);
            s[j][2] = __expf(s[j][2] - m1);
            s[j][3] = __expf(s[j][3] - m1);
            rs0 += s[j][0] + s[j][1];
            rs1 += s[j][2] + s[j][3];
        }
        rs0 += __shfl_xor_sync(0xffffffffu, rs0, 1);
        rs0 += __shfl_xor_sync(0xffffffffu, rs0, 2);
        rs1 += __shfl_xor_sync(0xffffffffu, rs1, 1);
        rs1 += __shfl_xor_sync(0xffffffffu, rs1, 2);
        l0 = l0 * a0 + rs0;
        l1 = l1 * a1 + rs1;

        unsigned pa[4][4];
        #pragma unroll
        for (int kk = 0; kk < 4; kk++) {
            pa[kk][0] = packbf2(s[2 * kk][0],     s[2 * kk][1]);
            pa[kk][1] = packbf2(s[2 * kk][2],     s[2 * kk][3]);
            pa[kk][2] = packbf2(s[2 * kk + 1][0], s[2 * kk + 1][1]);
            pa[kk][3] = packbf2(s[2 * kk + 1][2], s[2 * kk + 1][3]);
        }

        #pragma unroll
        for (int j = 0; j < 8; j++) {
            o[j][0] *= a0; o[j][1] *= a0; o[j][2] *= a1; o[j][3] *= a1;
        }

        const unsigned vb = smV + buf * 8192;
        #pragma unroll
        for (int kk = 0; kk < 4; kk++) {
            #pragma unroll
            for (int jp = 0; jp < 4; jp++) {
                unsigned vf[4];
                ldm_x4t(vf[0], vf[1], vf[2], vf[3],
                        vb + swz128(kk * 16 + nt_k * 8 + nt_r, 2 * jp + nt_p));
                mma_bf16(o[2 * jp],     pa[kk], vf);
                mma_bf16(o[2 * jp + 1], pa[kk], vf + 2);
            }
        }

        if (it + 1 < NIT) {
            asm volatile("cp.async.wait_group 0;");
            __syncthreads();
        }
    }

    float inv0 = 1.f / l0, inv1 = 1.f / l1;
    int row0 = q0 + w * 16 + g;
    int row1 = row0 + 8;
    #pragma unroll
    for (int j = 0; j < 8; j++) {
        int col = j * 8 + 2 * t4;
        if (row0 < SEQ)
            *(__nv_bfloat162*)(out + ((size_t)b * SEQ + row0) * HID + h * HDIM + col) =
                __floats2bfloat162_rn(o[j][0] * inv0, o[j][1] * inv0);
        if (row1 < SEQ)
            *(__nv_bfloat162*)(out + ((size_t)b * SEQ + row1) * HID + h * HDIM + col) =
                __floats2bfloat162_rn(o[j][2] * inv1, o[j][3] * inv1);
    }
}

// ---------------------------------------------------------------------------
extern "C" void kernel_launch(void* const* d_in, const int* in_sizes, int n_in,
                              void* d_out, int out_size) {
    const float* hidden = (const float*)d_in[0];
    const float* n1g    = (const float*)d_in[1];
    const float* n1b    = (const float*)d_in[2];
    const float* qkvw   = (const float*)d_in[3];
    const float* qkvb   = (const float*)d_in[4];
    const float* projw  = (const float*)d_in[5];
    const float* projb  = (const float*)d_in[6];
    const float* ls1    = (const float*)d_in[7];
    const float* n2g    = (const float*)d_in[8];
    const float* n2b    = (const float*)d_in[9];
    const float* fc1w   = (const float*)d_in[10];
    const float* fc1b   = (const float*)d_in[11];
    const float* fc2w   = (const float*)d_in[12];
    const float* fc2b   = (const float*)d_in[13];
    const float* ls2    = (const float*)d_in[14];
    float* out = (float*)d_out;

    __nv_bfloat16 *xnorm, *qkv, *attn, *mlp, *qkvw_bf, *projw_bf, *fc1w_bf, *fc2w_bf;
    cudaGetSymbolAddress((void**)&xnorm,    g_xnorm);
    cudaGetSymbolAddress((void**)&qkv,      g_qkv);
    cudaGetSymbolAddress((void**)&attn,     g_attn);
    cudaGetSymbolAddress((void**)&mlp,      g_mlp);
    cudaGetSymbolAddress((void**)&qkvw_bf,  g_qkvw);
    cudaGetSymbolAddress((void**)&projw_bf, g_projw);
    cudaGetSymbolAddress((void**)&fc1w_bf,  g_fc1w);
    cudaGetSymbolAddress((void**)&fc2w_bf,  g_fc2w);

    cudaFuncSetAttribute(gemm_bf16<1>, cudaFuncAttributeMaxDynamicSharedMemorySize, GSM_BYTES);
    cudaFuncSetAttribute(gemm_bf16<2>, cudaFuncAttributeMaxDynamicSharedMemorySize, GSM_BYTES);
    cudaFuncSetAttribute(gemm_bf16<3>, cudaFuncAttributeMaxDynamicSharedMemorySize, GSM_BYTES);

    const int MT = (M_TOK + 127) / 128;  // 129
    const int QT = (SEQ + 127) / 128;    // 9

    // 0. weight conversion fp32 -> bf16
    {
        int n;
        n = 3 * HID * HID / 4; f2bf_k<<<(n + 255) / 256, 256>>>(qkvw, qkvw_bf, n);
        n = HID * HID / 4;     f2bf_k<<<(n + 255) / 256, 256>>>(projw, projw_bf, n);
        n = IMED * HID / 4;    f2bf_k<<<(n + 255) / 256, 256>>>(fc1w, fc1w_bf, n);
        n = HID * IMED / 4;    f2bf_k<<<(n + 255) / 256, 256>>>(fc2w, fc2w_bf, n);
    }

    // 1. LN1 -> bf16
    layernorm_k<<<M_TOK, 256>>>(hidden, n1g, n1b, xnorm);
    // 2. QKV -> bf16
    gemm_bf16<1><<<dim3(3 * HID / 128, MT), 256, GSM_BYTES>>>(
        xnorm, qkvw_bf, qkvb, nullptr, nullptr, nullptr, qkv, M_TOK, 3 * HID, HID);
    // 3-5. fused attention
    flash_attn<<<dim3(QT, BATCH * NHEADS), 256>>>(qkv, attn);
    // 6. proj + ls1 residual -> d_out (fp32)
    gemm_bf16<3><<<dim3(HID / 128, MT), 256, GSM_BYTES>>>(
        attn, projw_bf, projb, ls1, hidden, out, nullptr, M_TOK, HID, HID);
    // 7. LN2 -> bf16
    layernorm_k<<<M_TOK, 256>>>(out, n2g, n2b, xnorm);
    // 8. fc1 + gelu -> bf16
    gemm_bf16<2><<<dim3(IMED / 128, MT), 256, GSM_BYTES>>>(
        xnorm, fc1w_bf, fc1b, nullptr, nullptr, nullptr, mlp, M_TOK, IMED, HID);
    // 9. fc2 + ls2 residual -> d_out (fp32, in place)
    gemm_bf16<3><<<dim3(HID / 128, MT), 256, GSM_BYTES>>>(
        mlp, fc2w_bf, fc2b, ls2, out, out, nullptr, M_TOK, HID, IMED);
}

// round 14
// speedup vs baseline: 1.1578x; 1.0045x over previous
#include <cuda_runtime.h>
#include <cuda_bf16.h>
#include <math.h>

// ---------------------------------------------------------------------------
// InternVisionLayer: B=16, S=1025, H=1024, NH=16, HD=64, I=4096, M = 16400
// R13: flash trims (exact-arithmetic): Q pre-scaled by 0.125 in QKV epilogue
//      (power-of-2 -> bit-exact, kills the S-scaling loop in flash); fused
//      exp+sum+pack loop shrinks register live range. Dense GEMMs = R12.
// ---------------------------------------------------------------------------

#define M_TOK   16400
#define SEQ     1025
#define BATCH   16
#define HID     1024
#define NHEADS  16
#define HDIM    64
#define IMED    4096

__device__ __nv_bfloat16 g_xnorm [(size_t)M_TOK * HID];
__device__ __nv_bfloat16 g_qkv   [(size_t)M_TOK * 3 * HID];
__device__ __nv_bfloat16 g_attn  [(size_t)M_TOK * HID];
__device__ __nv_bfloat16 g_mlp   [(size_t)M_TOK * IMED];
__device__ __nv_bfloat16 g_qkvw  [(size_t)3 * HID * HID];
__device__ __nv_bfloat16 g_projw [(size_t)HID * HID];
__device__ __nv_bfloat16 g_fc1w  [(size_t)IMED * HID];
__device__ __nv_bfloat16 g_fc2w  [(size_t)HID * IMED];

// ---------------------------------------------------------------------------
// helpers
// ---------------------------------------------------------------------------
__device__ __forceinline__ void mma_bf16(float* d, const unsigned* a, const unsigned* b) {
    asm volatile(
        "mma.sync.aligned.m16n8k16.row.col.f32.bf16.bf16.f32 "
        "{%0,%1,%2,%3}, {%4,%5,%6,%7}, {%8,%9}, {%0,%1,%2,%3};"
        : "+f"(d[0]), "+f"(d[1]), "+f"(d[2]), "+f"(d[3])
        : "r"(a[0]), "r"(a[1]), "r"(a[2]), "r"(a[3]), "r"(b[0]), "r"(b[1]));
}

__device__ __forceinline__ void ldm_x4(unsigned& r0, unsigned& r1, unsigned& r2,
                                       unsigned& r3, unsigned saddr) {
    asm volatile("ldmatrix.sync.aligned.m8n8.x4.shared.b16 {%0,%1,%2,%3}, [%4];"
                 : "=r"(r0), "=r"(r1), "=r"(r2), "=r"(r3) : "r"(saddr));
}
__device__ __forceinline__ void ldm_x4t(unsigned& r0, unsigned& r1, unsigned& r2,
                                        unsigned& r3, unsigned saddr) {
    asm volatile("ldmatrix.sync.aligned.m8n8.x4.trans.shared.b16 {%0,%1,%2,%3}, [%4];"
                 : "=r"(r0), "=r"(r1), "=r"(r2), "=r"(r3) : "r"(saddr));
}

__device__ __forceinline__ void cp16s(unsigned sa, const void* gsrc) {
    asm volatile("cp.async.cg.shared.global [%0], [%1], 16;\n"
                 :: "r"(sa), "l"(gsrc));
}
__device__ __forceinline__ void cp_commit() { asm volatile("cp.async.commit_group;"); }

__device__ __forceinline__ float gelu_f(float v) {
    return 0.5f * v * (1.0f + erff(v * 0.70710678118654752f));
}

__device__ __forceinline__ unsigned packbf2(float lo, float hi) {
    __nv_bfloat162 p = __floats2bfloat162_rn(lo, hi);
    return *(unsigned*)&p;
}

// 128-byte rows, 8 x 16B chunks, XOR swizzle (conflict-free for ldmatrix)
__device__ __forceinline__ unsigned swz128(int r, int c) {
    return (unsigned)(r * 128 + (((c ^ r) & 7) << 4));
}

// ---------------------------------------------------------------------------
// fp32 -> bf16 converter (weights)
// ---------------------------------------------------------------------------
__global__ void f2bf_k(const float* __restrict__ in, __nv_bfloat16* __restrict__ out,
                       int n4) {
    int i = blockIdx.x * blockDim.x + threadIdx.x;
    if (i < n4) {
        float4 v = ((const float4*)in)[i];
        ((__nv_bfloat162*)out)[2 * i + 0] = __floats2bfloat162_rn(v.x, v.y);
        ((__nv_bfloat162*)out)[2 * i + 1] = __floats2bfloat162_rn(v.z, v.w);
    }
}

// ---------------------------------------------------------------------------
// LayerNorm: one block (256 threads) per row of 1024; bf16 output
// ---------------------------------------------------------------------------
__global__ void layernorm_k(const float* __restrict__ x,
                            const float* __restrict__ g,
                            const float* __restrict__ b,
                            __nv_bfloat16* __restrict__ out) {
    int row = blockIdx.x;
    int t = threadIdx.x;
    const float4* xr = (const float4*)(x + (size_t)row * HID);
    float4 v = xr[t];
    float s  = v.x + v.y + v.z + v.w;
    float ss = v.x*v.x + v.y*v.y + v.z*v.z + v.w*v.w;
    #pragma unroll
    for (int o = 16; o; o >>= 1) {
        s  += __shfl_xor_sync(0xffffffffu, s,  o);
        ss += __shfl_xor_sync(0xffffffffu, ss, o);
    }
    __shared__ float sh[16];
    if ((t & 31) == 0) { sh[t >> 5] = s; sh[8 + (t >> 5)] = ss; }
    __syncthreads();
    s = 0.f; ss = 0.f;
    #pragma unroll
    for (int i = 0; i < 8; i++) { s += sh[i]; ss += sh[8 + i]; }
    float mean = s * (1.0f / HID);
    float var  = ss * (1.0f / HID) - mean * mean;
    float inv  = rsqrtf(var + 1e-5f);
    float4 gv = ((const float4*)g)[t];
    float4 bv = ((const float4*)b)[t];
    __nv_bfloat162* orow = (__nv_bfloat162*)(out + (size_t)row * HID);
    orow[2 * t + 0] = __floats2bfloat162_rn((v.x - mean) * inv * gv.x + bv.x,
                                            (v.y - mean) * inv * gv.y + bv.y);
    orow[2 * t + 1] = __floats2bfloat162_rn((v.z - mean) * inv * gv.z + bv.z,
                                            (v.w - mean) * inv * gv.w + bv.w);
}

// ---------------------------------------------------------------------------
// bf16 MMA GEMM: C = A[M,K] * B[N,K]^T, CTA 128x128, 8 warps of 64x32.
// K-chunk 64 (128B rows, swz128), 3-stage cp.async ring, ONE barrier/chunk.
// MODE 1: (v+bias)*blk_scale -> bf16   (blk_scale = 0.125 for q-tiles of QKV)
// MODE 2: +bias, gelu -> bf16
// MODE 3: resid + ls*( . + bias ) -> fp32
// ---------------------------------------------------------------------------
#define GSM_STAGE 32768
#define GSM_BYTES (3 * GSM_STAGE)

template <int MODE>
__global__ void __launch_bounds__(256, 2)
gemm_bf16(const __nv_bfloat16* __restrict__ A, const __nv_bfloat16* __restrict__ Bw,
          const float* __restrict__ bias, const float* __restrict__ ls,
          const float* __restrict__ resid, float* __restrict__ Cf,
          __nv_bfloat16* __restrict__ Cb, int M, int N, int K, int qcut) {
    extern __shared__ __align__(128) char smx[];

    const int t  = threadIdx.x;
    const int w  = t >> 5;
    const int lane = t & 31;
    const int g  = lane >> 2;
    const int t4 = lane & 3;
    const int wm = (w >> 2) * 64;
    const int wn = (w & 3) * 32;
    const int m0 = blockIdx.y * 128;
    const int n0 = blockIdx.x * 128;

    const unsigned smb = (unsigned)__cvta_generic_to_shared(smx);

    // whole 128-wide tile is either fully inside or outside [0, qcut)
    const float blk_scale = (MODE == 1 && n0 < qcut) ? 0.125f : 1.0f;

    float d[4][4][4];
    #pragma unroll
    for (int i = 0; i < 4; i++)
        #pragma unroll
        for (int j = 0; j < 4; j++)
            #pragma unroll
            for (int r = 0; r < 4; r++) d[i][j][r] = 0.f;

    auto stage = [&](int sg, int k0) {
        unsigned ab = smb + sg * GSM_STAGE;
        unsigned bb = ab + 16384;
        #pragma unroll
        for (int i = 0; i < 4; i++) {
            int id = t + i * 256;
            int r = id >> 3, c = id & 7;
            int rm = min(m0 + r, M - 1);
            cp16s(ab + swz128(r, c), A  + (size_t)rm * K + k0 + c * 8);
            cp16s(bb + swz128(r, c), Bw + (size_t)(n0 + r) * K + k0 + c * 8);
        }
    };

    const int a_row = (lane & 15);
    const int a_c   = (lane >> 4);
    const int b_row = ((lane >> 4) << 3) + (lane & 7);
    const int b_c   = ((lane >> 3) & 1);

    const int NC = K >> 6;
    stage(0, 0);  cp_commit();
    stage(1, 64); cp_commit();

    int cs = 0, ss = 2;
    for (int kc = 0; kc < NC; kc++) {
        asm volatile("cp.async.wait_group 1;");
        __syncthreads();

        if (kc + 2 < NC) stage(ss, (kc + 2) << 6);
        cp_commit();

        const unsigned ab = smb + cs * GSM_STAGE;
        const unsigned bb = ab + 16384;
        #pragma unroll
        for (int s = 0; s < 4; s++) {
            unsigned af[4][4], bf[2][4];
            #pragma unroll
            for (int i = 0; i < 4; i++)
                ldm_x4(af[i][0], af[i][1], af[i][2], af[i][3],
                       ab + swz128(wm + i * 16 + a_row, 2 * s + a_c));
            #pragma unroll
            for (int jj = 0; jj < 2; jj++)
                ldm_x4(bf[jj][0], bf[jj][1], bf[jj][2], bf[jj][3],
                       bb + swz128(wn + jj * 16 + b_row, 2 * s + b_c));
            #pragma unroll
            for (int i = 0; i < 4; i++)
                #pragma unroll
                for (int j = 0; j < 4; j++)
                    mma_bf16(d[i][j], af[i], &bf[j >> 1][(j & 1) * 2]);
        }
        cs = (cs == 2) ? 0 : cs + 1;
        ss = (ss == 2) ? 0 : ss + 1;
    }

    #pragma unroll
    for (int i = 0; i < 4; i++) {
        int rbase = m0 + wm + i * 16 + g;
        #pragma unroll
        for (int rr = 0; rr < 2; rr++) {
            int row = rbase + 8 * rr;
            if (row >= M) continue;
            #pragma unroll
            for (int j = 0; j < 4; j++) {
                int col = n0 + wn + j * 8 + 2 * t4;
                float v0 = d[i][j][rr * 2 + 0];
                float v1 = d[i][j][rr * 2 + 1];
                size_t idx = (size_t)row * N + col;
                if (MODE == 1) {
                    v0 = (v0 + bias[col])     * blk_scale;
                    v1 = (v1 + bias[col + 1]) * blk_scale;
                    *(__nv_bfloat162*)(Cb + idx) = __floats2bfloat162_rn(v0, v1);
                } else if (MODE == 2) {
                    v0 = gelu_f(v0 + bias[col]);
                    v1 = gelu_f(v1 + bias[col + 1]);
                    *(__nv_bfloat162*)(Cb + idx) = __floats2bfloat162_rn(v0, v1);
                } else {
                    float2 rv = *(const float2*)(resid + idx);
                    v0 = rv.x + ls[col]     * (v0 + bias[col]);
                    v1 = rv.y + ls[col + 1] * (v1 + bias[col + 1]);
                    *(float2*)(Cf + idx) = make_float2(v0, v1);
                }
            }
        }
    }
}

// ---------------------------------------------------------------------------
// bf16 flash attention. CTA = (q-tile 128, b*h). Q arrives pre-scaled by
// 0.125 (done in QKV epilogue; exact power-of-2). Fused exp+sum+pack loop.
// ---------------------------------------------------------------------------
#define NIT 17

__global__ void __launch_bounds__(256, 1)
flash_attn(const __nv_bfloat16* __restrict__ qkv, __nv_bfloat16* __restrict__ out) {
    __shared__ __align__(128) char sm[49152];
    const unsigned smb = (unsigned)__cvta_generic_to_shared(sm);
    const unsigned smK = smb + 16384;
    const unsigned smV = smb + 32768;

    const int t  = threadIdx.x;
    const int w  = t >> 5;
    const int lane = t & 31;
    const int g  = lane >> 2;
    const int t4 = lane & 3;
    const int q0 = blockIdx.x * 128;
    const int z  = blockIdx.y, b = z >> 4, h = z & 15;

    const __nv_bfloat16* Qg = qkv + (size_t)b * SEQ * (3 * HID) + h * HDIM;
    const __nv_bfloat16* Kg = Qg + HID;
    const __nv_bfloat16* Vg = Qg + 2 * HID;

    {
        #pragma unroll
        for (int i = 0; i < 4; i++) {
            int id = t + i * 256;
            int r = id >> 3, c = id & 7;
            int row = min(q0 + r, SEQ - 1);
            cp16s(smb + swz128(r, c), Qg + (size_t)row * (3 * HID) + c * 8);
        }
        #pragma unroll
        for (int i = 0; i < 2; i++) {
            int id = t + i * 256;
            int r = id >> 3, c = id & 7;
            cp16s(smK + swz128(r, c), Kg + (size_t)r * (3 * HID) + c * 8);
            cp16s(smV + swz128(r, c), Vg + (size_t)r * (3 * HID) + c * 8);
        }
        cp_commit();
        asm volatile("cp.async.wait_group 0;");
        __syncthreads();
    }

    unsigned qf[4][4];
    #pragma unroll
    for (int kc = 0; kc < 4; kc++)
        ldm_x4(qf[kc][0], qf[kc][1], qf[kc][2], qf[kc][3],
               smb + swz128(w * 16 + (lane & 15), kc * 2 + (lane >> 4)));

    float m0 = -1e30f, m1 = -1e30f, l0 = 0.f, l1 = 0.f;
    float o[8][4];
    #pragma unroll
    for (int j = 0; j < 8; j++)
        #pragma unroll
        for (int r = 0; r < 4; r++) o[j][r] = 0.f;

    const int nt_r = (lane & 7);
    const int nt_p = (lane >> 4);
    const int nt_k = ((lane >> 3) & 1);

    for (int it = 0; it < NIT; it++) {
        const int buf = it & 1;
        const int kv0 = it * 64;

        if (it + 1 < NIT) {
            int nb = buf ^ 1;
            #pragma unroll
            for (int i = 0; i < 2; i++) {
                int id = t + i * 256;
                int r = id >> 3, c = id & 7;
                int row = min(kv0 + 64 + r, SEQ - 1);
                cp16s(smK + nb * 8192 + swz128(r, c), Kg + (size_t)row * (3 * HID) + c * 8);
                cp16s(smV + nb * 8192 + swz128(r, c), Vg + (size_t)row * (3 * HID) + c * 8);
            }
            cp_commit();
        }

        // ---- S = (Q*0.125) K^T (scale already folded into Q) ----
        const unsigned kb = smK + buf * 8192;
        float s[8][4];
        #pragma unroll
        for (int j = 0; j < 8; j++)
            #pragma unroll
            for (int r = 0; r < 4; r++) s[j][r] = 0.f;
        #pragma unroll
        for (int kc = 0; kc < 4; kc++) {
            #pragma unroll
            for (int jp = 0; jp < 4; jp++) {
                unsigned kf[4];
                ldm_x4(kf[0], kf[1], kf[2], kf[3],
                       kb + swz128((2 * jp + nt_p) * 8 + nt_r, kc * 2 + nt_k));
                mma_bf16(s[2 * jp],     qf[kc], kf);
                mma_bf16(s[2 * jp + 1], qf[kc], kf + 2);
            }
        }

        // ---- tail mask (last tile only) ----
        const int lim = SEQ - kv0;
        if (lim < 64) {
            #pragma unroll
            for (int j = 0; j < 8; j++) {
                int cc = j * 8 + 2 * t4;
                if (cc     >= lim) { s[j][0] = -1e30f; s[j][2] = -1e30f; }
                if (cc + 1 >= lim) { s[j][1] = -1e30f; s[j][3] = -1e30f; }
            }
        }

        // ---- online softmax (rows g, g+8; quad-local reduction) ----
        float mx0 = -1e30f, mx1 = -1e30f;
        #pragma unroll
        for (int j = 0; j < 8; j++) {
            mx0 = fmaxf(mx0, fmaxf(s[j][0], s[j][1]));
            mx1 = fmaxf(mx1, fmaxf(s[j][2], s[j][3]));
        }
        mx0 = fmaxf(mx0, __shfl_xor_sync(0xffffffffu, mx0, 1));
        mx0 = fmaxf(mx0, __shfl_xor_sync(0xffffffffu, mx0, 2));
        mx1 = fmaxf(mx1, __shfl_xor_sync(0xffffffffu, mx1, 1));
        mx1 = fmaxf(mx1, __shfl_xor_sync(0xffffffffu, mx1, 2));

        float mn0 = fmaxf(m0, mx0), mn1 = fmaxf(m1, mx1);
        float a0 = __expf(m0 - mn0), a1 = __expf(m1 - mn1);
        m0 = mn0; m1 = mn1;

        // ---- fused exp + row-sum + pack (short s live range) ----
        unsigned pa[4][4];
        float rs0 = 0.f, rs1 = 0.f;
        #pragma unroll
        for (int kk = 0; kk < 4; kk++) {
            float e00 = __expf(s[2 * kk][0] - m0);
            float e01 = __expf(s[2 * kk][1] - m0);
            float e02 = __expf(s[2 * kk][2] - m1);
            float e03 = __expf(s[2 * kk][3] - m1);
            rs0 += e00 + e01;
            rs1 += e02 + e03;
            pa[kk][0] = packbf2(e00, e01);
            pa[kk][1] = packbf2(e02, e03);
            float e10 = __expf(s[2 * kk + 1][0] - m0);
            float e11 = __expf(s[2 * kk + 1][1] - m0);
            float e12 = __expf(s[2 * kk + 1][2] - m1);
            float e13 = __expf(s[2 * kk + 1][3] - m1);
            rs0 += e10 + e11;
            rs1 += e12 + e13;
            pa[kk][2] = packbf2(e10, e11);
            pa[kk][3] = packbf2(e12, e13);
        }
        rs0 += __shfl_xor_sync(0xffffffffu, rs0, 1);
        rs0 += __shfl_xor_sync(0xffffffffu, rs0, 2);
        rs1 += __shfl_xor_sync(0xffffffffu, rs1, 1);
        rs1 += __shfl_xor_sync(0xffffffffu, rs1, 2);
        l0 = l0 * a0 + rs0;
        l1 = l1 * a1 + rs1;

        // ---- rescale O ----
        #pragma unroll
        for (int j = 0; j < 8; j++) {
            o[j][0] *= a0; o[j][1] *= a0; o[j][2] *= a1; o[j][3] *= a1;
        }

        // ---- O += P V ----
        const unsigned vb = smV + buf * 8192;
        #pragma unroll
        for (int kk = 0; kk < 4; kk++) {
            #pragma unroll
            for (int jp = 0; jp < 4; jp++) {
                unsigned vf[4];
                ldm_x4t(vf[0], vf[1], vf[2], vf[3],
                        vb + swz128(kk * 16 + nt_k * 8 + nt_r, 2 * jp + nt_p));
                mma_bf16(o[2 * jp],     pa[kk], vf);
                mma_bf16(o[2 * jp + 1], pa[kk], vf + 2);
            }
        }

        if (it + 1 < NIT) {
            asm volatile("cp.async.wait_group 0;");
            __syncthreads();
        }
    }

    float inv0 = 1.f / l0, inv1 = 1.f / l1;
    int row0 = q0 + w * 16 + g;
    int row1 = row0 + 8;
    #pragma unroll
    for (int j = 0; j < 8; j++) {
        int col = j * 8 + 2 * t4;
        if (row0 < SEQ)
            *(__nv_bfloat162*)(out + ((size_t)b * SEQ + row0) * HID + h * HDIM + col) =
                __floats2bfloat162_rn(o[j][0] * inv0, o[j][1] * inv0);
        if (row1 < SEQ)
            *(__nv_bfloat162*)(out + ((size_t)b * SEQ + row1) * HID + h * HDIM + col) =
                __floats2bfloat162_rn(o[j][2] * inv1, o[j][3] * inv1);
    }
}

// ---------------------------------------------------------------------------
extern "C" void kernel_launch(void* const* d_in, const int* in_sizes, int n_in,
                              void* d_out, int out_size) {
    const float* hidden = (const float*)d_in[0];
    const float* n1g    = (const float*)d_in[1];
    const float* n1b    = (const float*)d_in[2];
    const float* qkvw   = (const float*)d_in[3];
    const float* qkvb   = (const float*)d_in[4];
    const float* projw  = (const float*)d_in[5];
    const float* projb  = (const float*)d_in[6];
    const float* ls1    = (const float*)d_in[7];
    const float* n2g    = (const float*)d_in[8];
    const float* n2b    = (const float*)d_in[9];
    const float* fc1w   = (const float*)d_in[10];
    const float* fc1b   = (const float*)d_in[11];
    const float* fc2w   = (const float*)d_in[12];
    const float* fc2b   = (const float*)d_in[13];
    const float* ls2    = (const float*)d_in[14];
    float* out = (float*)d_out;

    __nv_bfloat16 *xnorm, *qkv, *attn, *mlp, *qkvw_bf, *projw_bf, *fc1w_bf, *fc2w_bf;
    cudaGetSymbolAddress((void**)&xnorm,    g_xnorm);
    cudaGetSymbolAddress((void**)&qkv,      g_qkv);
    cudaGetSymbolAddress((void**)&attn,     g_attn);
    cudaGetSymbolAddress((void**)&mlp,      g_mlp);
    cudaGetSymbolAddress((void**)&qkvw_bf,  g_qkvw);
    cudaGetSymbolAddress((void**)&projw_bf, g_projw);
    cudaGetSymbolAddress((void**)&fc1w_bf,  g_fc1w);
    cudaGetSymbolAddress((void**)&fc2w_bf,  g_fc2w);

    cudaFuncSetAttribute(gemm_bf16<1>, cudaFuncAttributeMaxDynamicSharedMemorySize, GSM_BYTES);
    cudaFuncSetAttribute(gemm_bf16<2>, cudaFuncAttributeMaxDynamicSharedMemorySize, GSM_BYTES);
    cudaFuncSetAttribute(gemm_bf16<3>, cudaFuncAttributeMaxDynamicSharedMemorySize, GSM_BYTES);

    const int MT = (M_TOK + 127) / 128;  // 129
    const int QT = (SEQ + 127) / 128;    // 9

    // 0. weight conversion fp32 -> bf16
    {
        int n;
        n = 3 * HID * HID / 4; f2bf_k<<<(n + 255) / 256, 256>>>(qkvw, qkvw_bf, n);
        n = HID * HID / 4;     f2bf_k<<<(n + 255) / 256, 256>>>(projw, projw_bf, n);
        n = IMED * HID / 4;    f2bf_k<<<(n + 255) / 256, 256>>>(fc1w, fc1w_bf, n);
        n = HID * IMED / 4;    f2bf_k<<<(n + 255) / 256, 256>>>(fc2w, fc2w_bf, n);
    }

    // 1. LN1 -> bf16
    layernorm_k<<<M_TOK, 256>>>(hidden, n1g, n1b, xnorm);
    // 2. QKV -> bf16 (q columns pre-scaled by 0.125)
    gemm_bf16<1><<<dim3(3 * HID / 128, MT), 256, GSM_BYTES>>>(
        xnorm, qkvw_bf, qkvb, nullptr, nullptr, nullptr, qkv,
        M_TOK, 3 * HID, HID, HID);
    // 3-5. fused attention
    flash_attn<<<dim3(QT, BATCH * NHEADS), 256>>>(qkv, attn);
    // 6. proj + ls1 residual -> d_out (fp32)
    gemm_bf16<3><<<dim3(HID / 128, MT), 256, GSM_BYTES>>>(
        attn, projw_bf, projb, ls1, hidden, out, nullptr, M_TOK, HID, HID, 0);
    // 7. LN2 -> bf16
    layernorm_k<<<M_TOK, 256>>>(out, n2g, n2b, xnorm);
    // 8. fc1 + gelu -> bf16
    gemm_bf16<2><<<dim3(IMED / 128, MT), 256, GSM_BYTES>>>(
        xnorm, fc1w_bf, fc1b, nullptr, nullptr, nullptr, mlp,
        M_TOK, IMED, HID, 0);
    // 9. fc2 + ls2 residual -> d_out (fp32, in place)
    gemm_bf16<3><<<dim3(HID / 128, MT), 256, GSM_BYTES>>>(
        mlp, fc2w_bf, fc2b, ls2, out, out, nullptr, M_TOK, HID, IMED, 0);
}

// round 15
// speedup vs baseline: 1.2076x; 1.0430x over previous
#include <cuda_runtime.h>
#include <cuda_bf16.h>
#include <math.h>

// ---------------------------------------------------------------------------
// InternVisionLayer: B=16, S=1025, H=1024, NH=16, HD=64, I=4096, M = 16400
// R14: flash_attn -> launch_bounds(256, 2). R13's fused exp+sum+pack removed
//      the s+pa overlapping live range that made the 128-reg cap spill in R7;
//      peak live set now ~115 regs, so 2 CTAs/SM co-residency should be free
//      and cover the MUFU/shfl/barrier serial phases. All else = R13.
// ---------------------------------------------------------------------------

#define M_TOK   16400
#define SEQ     1025
#define BATCH   16
#define HID     1024
#define NHEADS  16
#define HDIM    64
#define IMED    4096

__device__ __nv_bfloat16 g_xnorm [(size_t)M_TOK * HID];
__device__ __nv_bfloat16 g_qkv   [(size_t)M_TOK * 3 * HID];
__device__ __nv_bfloat16 g_attn  [(size_t)M_TOK * HID];
__device__ __nv_bfloat16 g_mlp   [(size_t)M_TOK * IMED];
__device__ __nv_bfloat16 g_qkvw  [(size_t)3 * HID * HID];
__device__ __nv_bfloat16 g_projw [(size_t)HID * HID];
__device__ __nv_bfloat16 g_fc1w  [(size_t)IMED * HID];
__device__ __nv_bfloat16 g_fc2w  [(size_t)HID * IMED];

// ---------------------------------------------------------------------------
// helpers
// ---------------------------------------------------------------------------
__device__ __forceinline__ void mma_bf16(float* d, const unsigned* a, const unsigned* b) {
    asm volatile(
        "mma.sync.aligned.m16n8k16.row.col.f32.bf16.bf16.f32 "
        "{%0,%1,%2,%3}, {%4,%5,%6,%7}, {%8,%9}, {%0,%1,%2,%3};"
        : "+f"(d[0]), "+f"(d[1]), "+f"(d[2]), "+f"(d[3])
        : "r"(a[0]), "r"(a[1]), "r"(a[2]), "r"(a[3]), "r"(b[0]), "r"(b[1]));
}

__device__ __forceinline__ void ldm_x4(unsigned& r0, unsigned& r1, unsigned& r2,
                                       unsigned& r3, unsigned saddr) {
    asm volatile("ldmatrix.sync.aligned.m8n8.x4.shared.b16 {%0,%1,%2,%3}, [%4];"
                 : "=r"(r0), "=r"(r1), "=r"(r2), "=r"(r3) : "r"(saddr));
}
__device__ __forceinline__ void ldm_x4t(unsigned& r0, unsigned& r1, unsigned& r2,
                                        unsigned& r3, unsigned saddr) {
    asm volatile("ldmatrix.sync.aligned.m8n8.x4.trans.shared.b16 {%0,%1,%2,%3}, [%4];"
                 : "=r"(r0), "=r"(r1), "=r"(r2), "=r"(r3) : "r"(saddr));
}

__device__ __forceinline__ void cp16s(unsigned sa, const void* gsrc) {
    asm volatile("cp.async.cg.shared.global [%0], [%1], 16;\n"
                 :: "r"(sa), "l"(gsrc));
}
__device__ __forceinline__ void cp_commit() { asm volatile("cp.async.commit_group;"); }

__device__ __forceinline__ float gelu_f(float v) {
    return 0.5f * v * (1.0f + erff(v * 0.70710678118654752f));
}

__device__ __forceinline__ unsigned packbf2(float lo, float hi) {
    __nv_bfloat162 p = __floats2bfloat162_rn(lo, hi);
    return *(unsigned*)&p;
}

// 128-byte rows, 8 x 16B chunks, XOR swizzle (conflict-free for ldmatrix)
__device__ __forceinline__ unsigned swz128(int r, int c) {
    return (unsigned)(r * 128 + (((c ^ r) & 7) << 4));
}

// ---------------------------------------------------------------------------
// fp32 -> bf16 converter (weights)
// ---------------------------------------------------------------------------
__global__ void f2bf_k(const float* __restrict__ in, __nv_bfloat16* __restrict__ out,
                       int n4) {
    int i = blockIdx.x * blockDim.x + threadIdx.x;
    if (i < n4) {
        float4 v = ((const float4*)in)[i];
        ((__nv_bfloat162*)out)[2 * i + 0] = __floats2bfloat162_rn(v.x, v.y);
        ((__nv_bfloat162*)out)[2 * i + 1] = __floats2bfloat162_rn(v.z, v.w);
    }
}

// ---------------------------------------------------------------------------
// LayerNorm: one block (256 threads) per row of 1024; bf16 output
// ---------------------------------------------------------------------------
__global__ void layernorm_k(const float* __restrict__ x,
                            const float* __restrict__ g,
                            const float* __restrict__ b,
                            __nv_bfloat16* __restrict__ out) {
    int row = blockIdx.x;
    int t = threadIdx.x;
    const float4* xr = (const float4*)(x + (size_t)row * HID);
    float4 v = xr[t];
    float s  = v.x + v.y + v.z + v.w;
    float ss = v.x*v.x + v.y*v.y + v.z*v.z + v.w*v.w;
    #pragma unroll
    for (int o = 16; o; o >>= 1) {
        s  += __shfl_xor_sync(0xffffffffu, s,  o);
        ss += __shfl_xor_sync(0xffffffffu, ss, o);
    }
    __shared__ float sh[16];
    if ((t & 31) == 0) { sh[t >> 5] = s; sh[8 + (t >> 5)] = ss; }
    __syncthreads();
    s = 0.f; ss = 0.f;
    #pragma unroll
    for (int i = 0; i < 8; i++) { s += sh[i]; ss += sh[8 + i]; }
    float mean = s * (1.0f / HID);
    float var  = ss * (1.0f / HID) - mean * mean;
    float inv  = rsqrtf(var + 1e-5f);
    float4 gv = ((const float4*)g)[t];
    float4 bv = ((const float4*)b)[t];
    __nv_bfloat162* orow = (__nv_bfloat162*)(out + (size_t)row * HID);
    orow[2 * t + 0] = __floats2bfloat162_rn((v.x - mean) * inv * gv.x + bv.x,
                                            (v.y - mean) * inv * gv.y + bv.y);
    orow[2 * t + 1] = __floats2bfloat162_rn((v.z - mean) * inv * gv.z + bv.z,
                                            (v.w - mean) * inv * gv.w + bv.w);
}

// ---------------------------------------------------------------------------
// bf16 MMA GEMM: C = A[M,K] * B[N,K]^T, CTA 128x128, 8 warps of 64x32.
// K-chunk 64 (128B rows, swz128), 3-stage cp.async ring, ONE barrier/chunk.
// MODE 1: (v+bias)*blk_scale -> bf16   (blk_scale = 0.125 for q-tiles of QKV)
// MODE 2: +bias, gelu -> bf16
// MODE 3: resid + ls*( . + bias ) -> fp32
// ---------------------------------------------------------------------------
#define GSM_STAGE 32768
#define GSM_BYTES (3 * GSM_STAGE)

template <int MODE>
__global__ void __launch_bounds__(256, 2)
gemm_bf16(const __nv_bfloat16* __restrict__ A, const __nv_bfloat16* __restrict__ Bw,
          const float* __restrict__ bias, const float* __restrict__ ls,
          const float* __restrict__ resid, float* __restrict__ Cf,
          __nv_bfloat16* __restrict__ Cb, int M, int N, int K, int qcut) {
    extern __shared__ __align__(128) char smx[];

    const int t  = threadIdx.x;
    const int w  = t >> 5;
    const int lane = t & 31;
    const int g  = lane >> 2;
    const int t4 = lane & 3;
    const int wm = (w >> 2) * 64;
    const int wn = (w & 3) * 32;
    const int m0 = blockIdx.y * 128;
    const int n0 = blockIdx.x * 128;

    const unsigned smb = (unsigned)__cvta_generic_to_shared(smx);

    // whole 128-wide tile is either fully inside or outside [0, qcut)
    const float blk_scale = (MODE == 1 && n0 < qcut) ? 0.125f : 1.0f;

    float d[4][4][4];
    #pragma unroll
    for (int i = 0; i < 4; i++)
        #pragma unroll
        for (int j = 0; j < 4; j++)
            #pragma unroll
            for (int r = 0; r < 4; r++) d[i][j][r] = 0.f;

    auto stage = [&](int sg, int k0) {
        unsigned ab = smb + sg * GSM_STAGE;
        unsigned bb = ab + 16384;
        #pragma unroll
        for (int i = 0; i < 4; i++) {
            int id = t + i * 256;
            int r = id >> 3, c = id & 7;
            int rm = min(m0 + r, M - 1);
            cp16s(ab + swz128(r, c), A  + (size_t)rm * K + k0 + c * 8);
            cp16s(bb + swz128(r, c), Bw + (size_t)(n0 + r) * K + k0 + c * 8);
        }
    };

    const int a_row = (lane & 15);
    const int a_c   = (lane >> 4);
    const int b_row = ((lane >> 4) << 3) + (lane & 7);
    const int b_c   = ((lane >> 3) & 1);

    const int NC = K >> 6;
    stage(0, 0);  cp_commit();
    stage(1, 64); cp_commit();

    int cs = 0, ss = 2;
    for (int kc = 0; kc < NC; kc++) {
        asm volatile("cp.async.wait_group 1;");
        __syncthreads();

        if (kc + 2 < NC) stage(ss, (kc + 2) << 6);
        cp_commit();

        const unsigned ab = smb + cs * GSM_STAGE;
        const unsigned bb = ab + 16384;
        #pragma unroll
        for (int s = 0; s < 4; s++) {
            unsigned af[4][4], bf[2][4];
            #pragma unroll
            for (int i = 0; i < 4; i++)
                ldm_x4(af[i][0], af[i][1], af[i][2], af[i][3],
                       ab + swz128(wm + i * 16 + a_row, 2 * s + a_c));
            #pragma unroll
            for (int jj = 0; jj < 2; jj++)
                ldm_x4(bf[jj][0], bf[jj][1], bf[jj][2], bf[jj][3],
                       bb + swz128(wn + jj * 16 + b_row, 2 * s + b_c));
            #pragma unroll
            for (int i = 0; i < 4; i++)
                #pragma unroll
                for (int j = 0; j < 4; j++)
                    mma_bf16(d[i][j], af[i], &bf[j >> 1][(j & 1) * 2]);
        }
        cs = (cs == 2) ? 0 : cs + 1;
        ss = (ss == 2) ? 0 : ss + 1;
    }

    #pragma unroll
    for (int i = 0; i < 4; i++) {
        int rbase = m0 + wm + i * 16 + g;
        #pragma unroll
        for (int rr = 0; rr < 2; rr++) {
            int row = rbase + 8 * rr;
            if (row >= M) continue;
            #pragma unroll
            for (int j = 0; j < 4; j++) {
                int col = n0 + wn + j * 8 + 2 * t4;
                float v0 = d[i][j][rr * 2 + 0];
                float v1 = d[i][j][rr * 2 + 1];
                size_t idx = (size_t)row * N + col;
                if (MODE == 1) {
                    v0 = (v0 + bias[col])     * blk_scale;
                    v1 = (v1 + bias[col + 1]) * blk_scale;
                    *(__nv_bfloat162*)(Cb + idx) = __floats2bfloat162_rn(v0, v1);
                } else if (MODE == 2) {
                    v0 = gelu_f(v0 + bias[col]);
                    v1 = gelu_f(v1 + bias[col + 1]);
                    *(__nv_bfloat162*)(Cb + idx) = __floats2bfloat162_rn(v0, v1);
                } else {
                    float2 rv = *(const float2*)(resid + idx);
                    v0 = rv.x + ls[col]     * (v0 + bias[col]);
                    v1 = rv.y + ls[col + 1] * (v1 + bias[col + 1]);
                    *(float2*)(Cf + idx) = make_float2(v0, v1);
                }
            }
        }
    }
}

// ---------------------------------------------------------------------------
// bf16 flash attention. CTA = (q-tile 128, b*h). Q pre-scaled by 0.125.
// Fused exp+sum+pack loop (low live range) -> fits 128-reg cap; 2 CTAs/SM.
// ---------------------------------------------------------------------------
#define NIT 17

__global__ void __launch_bounds__(256, 2)
flash_attn(const __nv_bfloat16* __restrict__ qkv, __nv_bfloat16* __restrict__ out) {
    __shared__ __align__(128) char sm[49152];
    const unsigned smb = (unsigned)__cvta_generic_to_shared(sm);
    const unsigned smK = smb + 16384;
    const unsigned smV = smb + 32768;

    const int t  = threadIdx.x;
    const int w  = t >> 5;
    const int lane = t & 31;
    const int g  = lane >> 2;
    const int t4 = lane & 3;
    const int q0 = blockIdx.x * 128;
    const int z  = blockIdx.y, b = z >> 4, h = z & 15;

    const __nv_bfloat16* Qg = qkv + (size_t)b * SEQ * (3 * HID) + h * HDIM;
    const __nv_bfloat16* Kg = Qg + HID;
    const __nv_bfloat16* Vg = Qg + 2 * HID;

    {
        #pragma unroll
        for (int i = 0; i < 4; i++) {
            int id = t + i * 256;
            int r = id >> 3, c = id & 7;
            int row = min(q0 + r, SEQ - 1);
            cp16s(smb + swz128(r, c), Qg + (size_t)row * (3 * HID) + c * 8);
        }
        #pragma unroll
        for (int i = 0; i < 2; i++) {
            int id = t + i * 256;
            int r = id >> 3, c = id & 7;
            cp16s(smK + swz128(r, c), Kg + (size_t)r * (3 * HID) + c * 8);
            cp16s(smV + swz128(r, c), Vg + (size_t)r * (3 * HID) + c * 8);
        }
        cp_commit();
        asm volatile("cp.async.wait_group 0;");
        __syncthreads();
    }

    unsigned qf[4][4];
    #pragma unroll
    for (int kc = 0; kc < 4; kc++)
        ldm_x4(qf[kc][0], qf[kc][1], qf[kc][2], qf[kc][3],
               smb + swz128(w * 16 + (lane & 15), kc * 2 + (lane >> 4)));

    float m0 = -1e30f, m1 = -1e30f, l0 = 0.f, l1 = 0.f;
    float o[8][4];
    #pragma unroll
    for (int j = 0; j < 8; j++)
        #pragma unroll
        for (int r = 0; r < 4; r++) o[j][r] = 0.f;

    const int nt_r = (lane & 7);
    const int nt_p = (lane >> 4);
    const int nt_k = ((lane >> 3) & 1);

    for (int it = 0; it < NIT; it++) {
        const int buf = it & 1;
        const int kv0 = it * 64;

        if (it + 1 < NIT) {
            int nb = buf ^ 1;
            #pragma unroll
            for (int i = 0; i < 2; i++) {
                int id = t + i * 256;
                int r = id >> 3, c = id & 7;
                int row = min(kv0 + 64 + r, SEQ - 1);
                cp16s(smK + nb * 8192 + swz128(r, c), Kg + (size_t)row * (3 * HID) + c * 8);
                cp16s(smV + nb * 8192 + swz128(r, c), Vg + (size_t)row * (3 * HID) + c * 8);
            }
            cp_commit();
        }

        // ---- S = (Q*0.125) K^T (scale folded into Q) ----
        const unsigned kb = smK + buf * 8192;
        float s[8][4];
        #pragma unroll
        for (int j = 0; j < 8; j++)
            #pragma unroll
            for (int r = 0; r < 4; r++) s[j][r] = 0.f;
        #pragma unroll
        for (int kc = 0; kc < 4; kc++) {
            #pragma unroll
            for (int jp = 0; jp < 4; jp++) {
                unsigned kf[4];
                ldm_x4(kf[0], kf[1], kf[2], kf[3],
                       kb + swz128((2 * jp + nt_p) * 8 + nt_r, kc * 2 + nt_k));
                mma_bf16(s[2 * jp],     qf[kc], kf);
                mma_bf16(s[2 * jp + 1], qf[kc], kf + 2);
            }
        }

        // ---- tail mask (last tile only) ----
        const int lim = SEQ - kv0;
        if (lim < 64) {
            #pragma unroll
            for (int j = 0; j < 8; j++) {
                int cc = j * 8 + 2 * t4;
                if (cc     >= lim) { s[j][0] = -1e30f; s[j][2] = -1e30f; }
                if (cc + 1 >= lim) { s[j][1] = -1e30f; s[j][3] = -1e30f; }
            }
        }

        // ---- online softmax (rows g, g+8; quad-local reduction) ----
        float mx0 = -1e30f, mx1 = -1e30f;
        #pragma unroll
        for (int j = 0; j < 8; j++) {
            mx0 = fmaxf(mx0, fmaxf(s[j][0], s[j][1]));
            mx1 = fmaxf(mx1, fmaxf(s[j][2], s[j][3]));
        }
        mx0 = fmaxf(mx0, __shfl_xor_sync(0xffffffffu, mx0, 1));
        mx0 = fmaxf(mx0, __shfl_xor_sync(0xffffffffu, mx0, 2));
        mx1 = fmaxf(mx1, __shfl_xor_sync(0xffffffffu, mx1, 1));
        mx1 = fmaxf(mx1, __shfl_xor_sync(0xffffffffu, mx1, 2));

        float mn0 = fmaxf(m0, mx0), mn1 = fmaxf(m1, mx1);
        float a0 = __expf(m0 - mn0), a1 = __expf(m1 - mn1);
        m0 = mn0; m1 = mn1;

        // ---- fused exp + row-sum + pack (short s live range) ----
        unsigned pa[4][4];
        float rs0 = 0.f, rs1 = 0.f;
        #pragma unroll
        for (int kk = 0; kk < 4; kk++) {
            float e00 = __expf(s[2 * kk][0] - m0);
            float e01 = __expf(s[2 * kk][1] - m0);
            float e02 = __expf(s[2 * kk][2] - m1);
            float e03 = __expf(s[2 * kk][3] - m1);
            rs0 += e00 + e01;
            rs1 += e02 + e03;
            pa[kk][0] = packbf2(e00, e01);
            pa[kk][1] = packbf2(e02, e03);
            float e10 = __expf(s[2 * kk + 1][0] - m0);
            float e11 = __expf(s[2 * kk + 1][1] - m0);
            float e12 = __expf(s[2 * kk + 1][2] - m1);
            float e13 = __expf(s[2 * kk + 1][3] - m1);
            rs0 += e10 + e11;
            rs1 += e12 + e13;
            pa[kk][2] = packbf2(e10, e11);
            pa[kk][3] = packbf2(e12, e13);
        }
        rs0 += __shfl_xor_sync(0xffffffffu, rs0, 1);
        rs0 += __shfl_xor_sync(0xffffffffu, rs0, 2);
        rs1 += __shfl_xor_sync(0xffffffffu, rs1, 1);
        rs1 += __shfl_xor_sync(0xffffffffu, rs1, 2);
        l0 = l0 * a0 + rs0;
        l1 = l1 * a1 + rs1;

        // ---- rescale O ----
        #pragma unroll
        for (int j = 0; j < 8; j++) {
            o[j][0] *= a0; o[j][1] *= a0; o[j][2] *= a1; o[j][3] *= a1;
        }

        // ---- O += P V ----
        const unsigned vb = smV + buf * 8192;
        #pragma unroll
        for (int kk = 0; kk < 4; kk++) {
            #pragma unroll
            for (int jp = 0; jp < 4; jp++) {
                unsigned vf[4];
                ldm_x4t(vf[0], vf[1], vf[2], vf[3],
                        vb + swz128(kk * 16 + nt_k * 8 + nt_r, 2 * jp + nt_p));
                mma_bf16(o[2 * jp],     pa[kk], vf);
                mma_bf16(o[2 * jp + 1], pa[kk], vf + 2);
            }
        }

        if (it + 1 < NIT) {
            asm volatile("cp.async.wait_group 0;");
            __syncthreads();
        }
    }

    float inv0 = 1.f / l0, inv1 = 1.f / l1;
    int row0 = q0 + w * 16 + g;
    int row1 = row0 + 8;
    #pragma unroll
    for (int j = 0; j < 8; j++) {
        int col = j * 8 + 2 * t4;
        if (row0 < SEQ)
            *(__nv_bfloat162*)(out + ((size_t)b * SEQ + row0) * HID + h * HDIM + col) =
                __floats2bfloat162_rn(o[j][0] * inv0, o[j][1] * inv0);
        if (row1 < SEQ)
            *(__nv_bfloat162*)(out + ((size_t)b * SEQ + row1) * HID + h * HDIM + col) =
                __floats2bfloat162_rn(o[j][2] * inv1, o[j][3] * inv1);
    }
}

// ---------------------------------------------------------------------------
extern "C" void kernel_launch(void* const* d_in, const int* in_sizes, int n_in,
                              void* d_out, int out_size) {
    const float* hidden = (const float*)d_in[0];
    const float* n1g    = (const float*)d_in[1];
    const float* n1b    = (const float*)d_in[2];
    const float* qkvw   = (const float*)d_in[3];
    const float* qkvb   = (const float*)d_in[4];
    const float* projw  = (const float*)d_in[5];
    const float* projb  = (const float*)d_in[6];
    const float* ls1    = (const float*)d_in[7];
    const float* n2g    = (const float*)d_in[8];
    const float* n2b    = (const float*)d_in[9];
    const float* fc1w   = (const float*)d_in[10];
    const float* fc1b   = (const float*)d_in[11];
    const float* fc2w   = (const float*)d_in[12];
    const float* fc2b   = (const float*)d_in[13];
    const float* ls2    = (const float*)d_in[14];
    float* out = (float*)d_out;

    __nv_bfloat16 *xnorm, *qkv, *attn, *mlp, *qkvw_bf, *projw_bf, *fc1w_bf, *fc2w_bf;
    cudaGetSymbolAddress((void**)&xnorm,    g_xnorm);
    cudaGetSymbolAddress((void**)&qkv,      g_qkv);
    cudaGetSymbolAddress((void**)&attn,     g_attn);
    cudaGetSymbolAddress((void**)&mlp,      g_mlp);
    cudaGetSymbolAddress((void**)&qkvw_bf,  g_qkvw);
    cudaGetSymbolAddress((void**)&projw_bf, g_projw);
    cudaGetSymbolAddress((void**)&fc1w_bf,  g_fc1w);
    cudaGetSymbolAddress((void**)&fc2w_bf,  g_fc2w);

    cudaFuncSetAttribute(gemm_bf16<1>, cudaFuncAttributeMaxDynamicSharedMemorySize, GSM_BYTES);
    cudaFuncSetAttribute(gemm_bf16<2>, cudaFuncAttributeMaxDynamicSharedMemorySize, GSM_BYTES);
    cudaFuncSetAttribute(gemm_bf16<3>, cudaFuncAttributeMaxDynamicSharedMemorySize, GSM_BYTES);

    const int MT = (M_TOK + 127) / 128;  // 129
    const int QT = (SEQ + 127) / 128;    // 9

    // 0. weight conversion fp32 -> bf16
    {
        int n;
        n = 3 * HID * HID / 4; f2bf_k<<<(n + 255) / 256, 256>>>(qkvw, qkvw_bf, n);
        n = HID * HID / 4;     f2bf_k<<<(n + 255) / 256, 256>>>(projw, projw_bf, n);
        n = IMED * HID / 4;    f2bf_k<<<(n + 255) / 256, 256>>>(fc1w, fc1w_bf, n);
        n = HID * IMED / 4;    f2bf_k<<<(n + 255) / 256, 256>>>(fc2w, fc2w_bf, n);
    }

    // 1. LN1 -> bf16
    layernorm_k<<<M_TOK, 256>>>(hidden, n1g, n1b, xnorm);
    // 2. QKV -> bf16 (q columns pre-scaled by 0.125)
    gemm_bf16<1><<<dim3(3 * HID / 128, MT), 256, GSM_BYTES>>>(
        xnorm, qkvw_bf, qkvb, nullptr, nullptr, nullptr, qkv,
        M_TOK, 3 * HID, HID, HID);
    // 3-5. fused attention
    flash_attn<<<dim3(QT, BATCH * NHEADS), 256>>>(qkv, attn);
    // 6. proj + ls1 residual -> d_out (fp32)
    gemm_bf16<3><<<dim3(HID / 128, MT), 256, GSM_BYTES>>>(
        attn, projw_bf, projb, ls1, hidden, out, nullptr, M_TOK, HID, HID, 0);
    // 7. LN2 -> bf16
    layernorm_k<<<M_TOK, 256>>>(out, n2g, n2b, xnorm);
    // 8. fc1 + gelu -> bf16
    gemm_bf16<2><<<dim3(IMED / 128, MT), 256, GSM_BYTES>>>(
        xnorm, fc1w_bf, fc1b, nullptr, nullptr, nullptr, mlp,
        M_TOK, IMED, HID, 0);
    // 9. fc2 + ls2 residual -> d_out (fp32, in place)
    gemm_bf16<3><<<dim3(HID / 128, MT), 256, GSM_BYTES>>>(
        mlp, fc2w_bf, fc2b, ls2, out, out, nullptr, M_TOK, HID, IMED, 0);
}

// round 16
// speedup vs baseline: 1.2224x; 1.0122x over previous
#include <cuda_runtime.h>
#include <cuda_bf16.h>
#include <math.h>

// ---------------------------------------------------------------------------
// InternVisionLayer: B=16, S=1025, H=1024, NH=16, HD=64, I=4096, M = 16400
// R15: (a) 4 f2bf weight-conversion launches merged into one kernel;
//      (b) flash: per-iteration l-reduction deferred to epilogue (linearity:
//      a0/a1 are quad-uniform, so quad partials sum exactly at the end).
//      All else identical to R14 (1367us).
// ---------------------------------------------------------------------------

#define M_TOK   16400
#define SEQ     1025
#define BATCH   16
#define HID     1024
#define NHEADS  16
#define HDIM    64
#define IMED    4096

__device__ __nv_bfloat16 g_xnorm [(size_t)M_TOK * HID];
__device__ __nv_bfloat16 g_qkv   [(size_t)M_TOK * 3 * HID];
__device__ __nv_bfloat16 g_attn  [(size_t)M_TOK * HID];
__device__ __nv_bfloat16 g_mlp   [(size_t)M_TOK * IMED];
__device__ __nv_bfloat16 g_qkvw  [(size_t)3 * HID * HID];
__device__ __nv_bfloat16 g_projw [(size_t)HID * HID];
__device__ __nv_bfloat16 g_fc1w  [(size_t)IMED * HID];
__device__ __nv_bfloat16 g_fc2w  [(size_t)HID * IMED];

// ---------------------------------------------------------------------------
// helpers
// ---------------------------------------------------------------------------
__device__ __forceinline__ void mma_bf16(float* d, const unsigned* a, const unsigned* b) {
    asm volatile(
        "mma.sync.aligned.m16n8k16.row.col.f32.bf16.bf16.f32 "
        "{%0,%1,%2,%3}, {%4,%5,%6,%7}, {%8,%9}, {%0,%1,%2,%3};"
        : "+f"(d[0]), "+f"(d[1]), "+f"(d[2]), "+f"(d[3])
        : "r"(a[0]), "r"(a[1]), "r"(a[2]), "r"(a[3]), "r"(b[0]), "r"(b[1]));
}

__device__ __forceinline__ void ldm_x4(unsigned& r0, unsigned& r1, unsigned& r2,
                                       unsigned& r3, unsigned saddr) {
    asm volatile("ldmatrix.sync.aligned.m8n8.x4.shared.b16 {%0,%1,%2,%3}, [%4];"
                 : "=r"(r0), "=r"(r1), "=r"(r2), "=r"(r3) : "r"(saddr));
}
__device__ __forceinline__ void ldm_x4t(unsigned& r0, unsigned& r1, unsigned& r2,
                                        unsigned& r3, unsigned saddr) {
    asm volatile("ldmatrix.sync.aligned.m8n8.x4.trans.shared.b16 {%0,%1,%2,%3}, [%4];"
                 : "=r"(r0), "=r"(r1), "=r"(r2), "=r"(r3) : "r"(saddr));
}

__device__ __forceinline__ void cp16s(unsigned sa, const void* gsrc) {
    asm volatile("cp.async.cg.shared.global [%0], [%1], 16;\n"
                 :: "r"(sa), "l"(gsrc));
}
__device__ __forceinline__ void cp_commit() { asm volatile("cp.async.commit_group;"); }

__device__ __forceinline__ float gelu_f(float v) {
    return 0.5f * v * (1.0f + erff(v * 0.70710678118654752f));
}

__device__ __forceinline__ unsigned packbf2(float lo, float hi) {
    __nv_bfloat162 p = __floats2bfloat162_rn(lo, hi);
    return *(unsigned*)&p;
}

// 128-byte rows, 8 x 16B chunks, XOR swizzle (conflict-free for ldmatrix)
__device__ __forceinline__ unsigned swz128(int r, int c) {
    return (unsigned)(r * 128 + (((c ^ r) & 7) << 4));
}

// ---------------------------------------------------------------------------
// Merged fp32 -> bf16 weight converter: one launch, 4 segments.
// Segment sizes in float4 units.
// ---------------------------------------------------------------------------
#define N4_QKVW (3 * HID * HID / 4)
#define N4_PROJ (HID * HID / 4)
#define N4_FC1  (IMED * HID / 4)
#define N4_FC2  (HID * IMED / 4)
#define N4_TOT  (N4_QKVW + N4_PROJ + N4_FC1 + N4_FC2)

__global__ void f2bf_all_k(const float* __restrict__ qkvw,
                           const float* __restrict__ projw,
                           const float* __restrict__ fc1w,
                           const float* __restrict__ fc2w,
                           __nv_bfloat16* __restrict__ o_qkvw,
                           __nv_bfloat16* __restrict__ o_projw,
                           __nv_bfloat16* __restrict__ o_fc1w,
                           __nv_bfloat16* __restrict__ o_fc2w) {
    int i = blockIdx.x * blockDim.x + threadIdx.x;
    if (i >= N4_TOT) return;
    const float* in;
    __nv_bfloat16* out;
    if (i < N4_QKVW) {
        in = qkvw; out = o_qkvw;
    } else if (i < N4_QKVW + N4_PROJ) {
        i -= N4_QKVW; in = projw; out = o_projw;
    } else if (i < N4_QKVW + N4_PROJ + N4_FC1) {
        i -= N4_QKVW + N4_PROJ; in = fc1w; out = o_fc1w;
    } else {
        i -= N4_QKVW + N4_PROJ + N4_FC1; in = fc2w; out = o_fc2w;
    }
    float4 v = ((const float4*)in)[i];
    ((__nv_bfloat162*)out)[2 * i + 0] = __floats2bfloat162_rn(v.x, v.y);
    ((__nv_bfloat162*)out)[2 * i + 1] = __floats2bfloat162_rn(v.z, v.w);
}

// ---------------------------------------------------------------------------
// LayerNorm: one block (256 threads) per row of 1024; bf16 output
// ---------------------------------------------------------------------------
__global__ void layernorm_k(const float* __restrict__ x,
                            const float* __restrict__ g,
                            const float* __restrict__ b,
                            __nv_bfloat16* __restrict__ out) {
    int row = blockIdx.x;
    int t = threadIdx.x;
    const float4* xr = (const float4*)(x + (size_t)row * HID);
    float4 v = xr[t];
    float s  = v.x + v.y + v.z + v.w;
    float ss = v.x*v.x + v.y*v.y + v.z*v.z + v.w*v.w;
    #pragma unroll
    for (int o = 16; o; o >>= 1) {
        s  += __shfl_xor_sync(0xffffffffu, s,  o);
        ss += __shfl_xor_sync(0xffffffffu, ss, o);
    }
    __shared__ float sh[16];
    if ((t & 31) == 0) { sh[t >> 5] = s; sh[8 + (t >> 5)] = ss; }
    __syncthreads();
    s = 0.f; ss = 0.f;
    #pragma unroll
    for (int i = 0; i < 8; i++) { s += sh[i]; ss += sh[8 + i]; }
    float mean = s * (1.0f / HID);
    float var  = ss * (1.0f / HID) - mean * mean;
    float inv  = rsqrtf(var + 1e-5f);
    float4 gv = ((const float4*)g)[t];
    float4 bv = ((const float4*)b)[t];
    __nv_bfloat162* orow = (__nv_bfloat162*)(out + (size_t)row * HID);
    orow[2 * t + 0] = __floats2bfloat162_rn((v.x - mean) * inv * gv.x + bv.x,
                                            (v.y - mean) * inv * gv.y + bv.y);
    orow[2 * t + 1] = __floats2bfloat162_rn((v.z - mean) * inv * gv.z + bv.z,
                                            (v.w - mean) * inv * gv.w + bv.w);
}

// ---------------------------------------------------------------------------
// bf16 MMA GEMM: C = A[M,K] * B[N,K]^T, CTA 128x128, 8 warps of 64x32.
// K-chunk 64 (128B rows, swz128), 3-stage cp.async ring, ONE barrier/chunk.
// MODE 1: (v+bias)*blk_scale -> bf16   (blk_scale = 0.125 for q-tiles of QKV)
// MODE 2: +bias, gelu -> bf16
// MODE 3: resid + ls*( . + bias ) -> fp32
// ---------------------------------------------------------------------------
#define GSM_STAGE 32768
#define GSM_BYTES (3 * GSM_STAGE)

template <int MODE>
__global__ void __launch_bounds__(256, 2)
gemm_bf16(const __nv_bfloat16* __restrict__ A, const __nv_bfloat16* __restrict__ Bw,
          const float* __restrict__ bias, const float* __restrict__ ls,
          const float* __restrict__ resid, float* __restrict__ Cf,
          __nv_bfloat16* __restrict__ Cb, int M, int N, int K, int qcut) {
    extern __shared__ __align__(128) char smx[];

    const int t  = threadIdx.x;
    const int w  = t >> 5;
    const int lane = t & 31;
    const int g  = lane >> 2;
    const int t4 = lane & 3;
    const int wm = (w >> 2) * 64;
    const int wn = (w & 3) * 32;
    const int m0 = blockIdx.y * 128;
    const int n0 = blockIdx.x * 128;

    const unsigned smb = (unsigned)__cvta_generic_to_shared(smx);

    const float blk_scale = (MODE == 1 && n0 < qcut) ? 0.125f : 1.0f;

    float d[4][4][4];
    #pragma unroll
    for (int i = 0; i < 4; i++)
        #pragma unroll
        for (int j = 0; j < 4; j++)
            #pragma unroll
            for (int r = 0; r < 4; r++) d[i][j][r] = 0.f;

    auto stage = [&](int sg, int k0) {
        unsigned ab = smb + sg * GSM_STAGE;
        unsigned bb = ab + 16384;
        #pragma unroll
        for (int i = 0; i < 4; i++) {
            int id = t + i * 256;
            int r = id >> 3, c = id & 7;
            int rm = min(m0 + r, M - 1);
            cp16s(ab + swz128(r, c), A  + (size_t)rm * K + k0 + c * 8);
            cp16s(bb + swz128(r, c), Bw + (size_t)(n0 + r) * K + k0 + c * 8);
        }
    };

    const int a_row = (lane & 15);
    const int a_c   = (lane >> 4);
    const int b_row = ((lane >> 4) << 3) + (lane & 7);
    const int b_c   = ((lane >> 3) & 1);

    const int NC = K >> 6;
    stage(0, 0);  cp_commit();
    stage(1, 64); cp_commit();

    int cs = 0, ss = 2;
    for (int kc = 0; kc < NC; kc++) {
        asm volatile("cp.async.wait_group 1;");
        __syncthreads();

        if (kc + 2 < NC) stage(ss, (kc + 2) << 6);
        cp_commit();

        const unsigned ab = smb + cs * GSM_STAGE;
        const unsigned bb = ab + 16384;
        #pragma unroll
        for (int s = 0; s < 4; s++) {
            unsigned af[4][4], bf[2][4];
            #pragma unroll
            for (int i = 0; i < 4; i++)
                ldm_x4(af[i][0], af[i][1], af[i][2], af[i][3],
                       ab + swz128(wm + i * 16 + a_row, 2 * s + a_c));
            #pragma unroll
            for (int jj = 0; jj < 2; jj++)
                ldm_x4(bf[jj][0], bf[jj][1], bf[jj][2], bf[jj][3],
                       bb + swz128(wn + jj * 16 + b_row, 2 * s + b_c));
            #pragma unroll
            for (int i = 0; i < 4; i++)
                #pragma unroll
                for (int j = 0; j < 4; j++)
                    mma_bf16(d[i][j], af[i], &bf[j >> 1][(j & 1) * 2]);
        }
        cs = (cs == 2) ? 0 : cs + 1;
        ss = (ss == 2) ? 0 : ss + 1;
    }

    #pragma unroll
    for (int i = 0; i < 4; i++) {
        int rbase = m0 + wm + i * 16 + g;
        #pragma unroll
        for (int rr = 0; rr < 2; rr++) {
            int row = rbase + 8 * rr;
            if (row >= M) continue;
            #pragma unroll
            for (int j = 0; j < 4; j++) {
                int col = n0 + wn + j * 8 + 2 * t4;
                float v0 = d[i][j][rr * 2 + 0];
                float v1 = d[i][j][rr * 2 + 1];
                size_t idx = (size_t)row * N + col;
                if (MODE == 1) {
                    v0 = (v0 + bias[col])     * blk_scale;
                    v1 = (v1 + bias[col + 1]) * blk_scale;
                    *(__nv_bfloat162*)(Cb + idx) = __floats2bfloat162_rn(v0, v1);
                } else if (MODE == 2) {
                    v0 = gelu_f(v0 + bias[col]);
                    v1 = gelu_f(v1 + bias[col + 1]);
                    *(__nv_bfloat162*)(Cb + idx) = __floats2bfloat162_rn(v0, v1);
                } else {
                    float2 rv = *(const float2*)(resid + idx);
                    v0 = rv.x + ls[col]     * (v0 + bias[col]);
                    v1 = rv.y + ls[col + 1] * (v1 + bias[col + 1]);
                    *(float2*)(Cf + idx) = make_float2(v0, v1);
                }
            }
        }
    }
}

// ---------------------------------------------------------------------------
// bf16 flash attention. CTA = (q-tile 128, b*h). Q pre-scaled by 0.125.
// Fused exp+sum+pack; l-reduction deferred to epilogue (quad partials are
// exact by linearity since a0/a1 are quad-uniform). 2 CTAs/SM.
// ---------------------------------------------------------------------------
#define NIT 17

__global__ void __launch_bounds__(256, 2)
flash_attn(const __nv_bfloat16* __restrict__ qkv, __nv_bfloat16* __restrict__ out) {
    __shared__ __align__(128) char sm[49152];
    const unsigned smb = (unsigned)__cvta_generic_to_shared(sm);
    const unsigned smK = smb + 16384;
    const unsigned smV = smb + 32768;

    const int t  = threadIdx.x;
    const int w  = t >> 5;
    const int lane = t & 31;
    const int g  = lane >> 2;
    const int t4 = lane & 3;
    const int q0 = blockIdx.x * 128;
    const int z  = blockIdx.y, b = z >> 4, h = z & 15;

    const __nv_bfloat16* Qg = qkv + (size_t)b * SEQ * (3 * HID) + h * HDIM;
    const __nv_bfloat16* Kg = Qg + HID;
    const __nv_bfloat16* Vg = Qg + 2 * HID;

    {
        #pragma unroll
        for (int i = 0; i < 4; i++) {
            int id = t + i * 256;
            int r = id >> 3, c = id & 7;
            int row = min(q0 + r, SEQ - 1);
            cp16s(smb + swz128(r, c), Qg + (size_t)row * (3 * HID) + c * 8);
        }
        #pragma unroll
        for (int i = 0; i < 2; i++) {
            int id = t + i * 256;
            int r = id >> 3, c = id & 7;
            cp16s(smK + swz128(r, c), Kg + (size_t)r * (3 * HID) + c * 8);
            cp16s(smV + swz128(r, c), Vg + (size_t)r * (3 * HID) + c * 8);
        }
        cp_commit();
        asm volatile("cp.async.wait_group 0;");
        __syncthreads();
    }

    unsigned qf[4][4];
    #pragma unroll
    for (int kc = 0; kc < 4; kc++)
        ldm_x4(qf[kc][0], qf[kc][1], qf[kc][2], qf[kc][3],
               smb + swz128(w * 16 + (lane & 15), kc * 2 + (lane >> 4)));

    float m0 = -1e30f, m1 = -1e30f;
    float lp0 = 0.f, lp1 = 0.f;   // quad-PARTIAL l accumulators
    float o[8][4];
    #pragma unroll
    for (int j = 0; j < 8; j++)
        #pragma unroll
        for (int r = 0; r < 4; r++) o[j][r] = 0.f;

    const int nt_r = (lane & 7);
    const int nt_p = (lane >> 4);
    const int nt_k = ((lane >> 3) & 1);

    for (int it = 0; it < NIT; it++) {
        const int buf = it & 1;
        const int kv0 = it * 64;

        if (it + 1 < NIT) {
            int nb = buf ^ 1;
            #pragma unroll
            for (int i = 0; i < 2; i++) {
                int id = t + i * 256;
                int r = id >> 3, c = id & 7;
                int row = min(kv0 + 64 + r, SEQ - 1);
                cp16s(smK + nb * 8192 + swz128(r, c), Kg + (size_t)row * (3 * HID) + c * 8);
                cp16s(smV + nb * 8192 + swz128(r, c), Vg + (size_t)row * (3 * HID) + c * 8);
            }
            cp_commit();
        }

        // ---- S = (Q*0.125) K^T ----
        const unsigned kb = smK + buf * 8192;
        float s[8][4];
        #pragma unroll
        for (int j = 0; j < 8; j++)
            #pragma unroll
            for (int r = 0; r < 4; r++) s[j][r] = 0.f;
        #pragma unroll
        for (int kc = 0; kc < 4; kc++) {
            #pragma unroll
            for (int jp = 0; jp < 4; jp++) {
                unsigned kf[4];
                ldm_x4(kf[0], kf[1], kf[2], kf[3],
                       kb + swz128((2 * jp + nt_p) * 8 + nt_r, kc * 2 + nt_k));
                mma_bf16(s[2 * jp],     qf[kc], kf);
                mma_bf16(s[2 * jp + 1], qf[kc], kf + 2);
            }
        }

        // ---- tail mask (last tile only) ----
        const int lim = SEQ - kv0;
        if (lim < 64) {
            #pragma unroll
            for (int j = 0; j < 8; j++) {
                int cc = j * 8 + 2 * t4;
                if (cc     >= lim) { s[j][0] = -1e30f; s[j][2] = -1e30f; }
                if (cc + 1 >= lim) { s[j][1] = -1e30f; s[j][3] = -1e30f; }
            }
        }

        // ---- online max (quad reduction; needed before exp) ----
        float mx0 = -1e30f, mx1 = -1e30f;
        #pragma unroll
        for (int j = 0; j < 8; j++) {
            mx0 = fmaxf(mx0, fmaxf(s[j][0], s[j][1]));
            mx1 = fmaxf(mx1, fmaxf(s[j][2], s[j][3]));
        }
        mx0 = fmaxf(mx0, __shfl_xor_sync(0xffffffffu, mx0, 1));
        mx0 = fmaxf(mx0, __shfl_xor_sync(0xffffffffu, mx0, 2));
        mx1 = fmaxf(mx1, __shfl_xor_sync(0xffffffffu, mx1, 1));
        mx1 = fmaxf(mx1, __shfl_xor_sync(0xffffffffu, mx1, 2));

        float mn0 = fmaxf(m0, mx0), mn1 = fmaxf(m1, mx1);
        float a0 = __expf(m0 - mn0), a1 = __expf(m1 - mn1);
        m0 = mn0; m1 = mn1;

        // ---- fused exp + quad-partial sum + pack (NO shfl here) ----
        unsigned pa[4][4];
        float rs0 = 0.f, rs1 = 0.f;
        #pragma unroll
        for (int kk = 0; kk < 4; kk++) {
            float e00 = __expf(s[2 * kk][0] - m0);
            float e01 = __expf(s[2 * kk][1] - m0);
            float e02 = __expf(s[2 * kk][2] - m1);
            float e03 = __expf(s[2 * kk][3] - m1);
            rs0 += e00 + e01;
            rs1 += e02 + e03;
            pa[kk][0] = packbf2(e00, e01);
            pa[kk][1] = packbf2(e02, e03);
            float e10 = __expf(s[2 * kk + 1][0] - m0);
            float e11 = __expf(s[2 * kk + 1][1] - m0);
            float e12 = __expf(s[2 * kk + 1][2] - m1);
            float e13 = __expf(s[2 * kk + 1][3] - m1);
            rs0 += e10 + e11;
            rs1 += e12 + e13;
            pa[kk][2] = packbf2(e10, e11);
            pa[kk][3] = packbf2(e12, e13);
        }
        // quad-partial online update (a0/a1 uniform across quad -> exact)
        lp0 = lp0 * a0 + rs0;
        lp1 = lp1 * a1 + rs1;

        // ---- rescale O ----
        #pragma unroll
        for (int j = 0; j < 8; j++) {
            o[j][0] *= a0; o[j][1] *= a0; o[j][2] *= a1; o[j][3] *= a1;
        }

        // ---- O += P V ----
        const unsigned vb = smV + buf * 8192;
        #pragma unroll
        for (int kk = 0; kk < 4; kk++) {
            #pragma unroll
            for (int jp = 0; jp < 4; jp++) {
                unsigned vf[4];
                ldm_x4t(vf[0], vf[1], vf[2], vf[3],
                        vb + swz128(kk * 16 + nt_k * 8 + nt_r, 2 * jp + nt_p));
                mma_bf16(o[2 * jp],     pa[kk], vf);
                mma_bf16(o[2 * jp + 1], pa[kk], vf + 2);
            }
        }

        if (it + 1 < NIT) {
            asm volatile("cp.async.wait_group 0;");
            __syncthreads();
        }
    }

    // ---- deferred l reduction (quad sum, once) ----
    float l0 = lp0, l1 = lp1;
    l0 += __shfl_xor_sync(0xffffffffu, l0, 1);
    l0 += __shfl_xor_sync(0xffffffffu, l0, 2);
    l1 += __shfl_xor_sync(0xffffffffu, l1, 1);
    l1 += __shfl_xor_sync(0xffffffffu, l1, 2);

    float inv0 = 1.f / l0, inv1 = 1.f / l1;
    int row0 = q0 + w * 16 + g;
    int row1 = row0 + 8;
    #pragma unroll
    for (int j = 0; j < 8; j++) {
        int col = j * 8 + 2 * t4;
        if (row0 < SEQ)
            *(__nv_bfloat162*)(out + ((size_t)b * SEQ + row0) * HID + h * HDIM + col) =
                __floats2bfloat162_rn(o[j][0] * inv0, o[j][1] * inv0);
        if (row1 < SEQ)
            *(__nv_bfloat162*)(out + ((size_t)b * SEQ + row1) * HID + h * HDIM + col) =
                __floats2bfloat162_rn(o[j][2] * inv1, o[j][3] * inv1);
    }
}

// ---------------------------------------------------------------------------
extern "C" void kernel_launch(void* const* d_in, const int* in_sizes, int n_in,
                              void* d_out, int out_size) {
    const float* hidden = (const float*)d_in[0];
    const float* n1g    = (const float*)d_in[1];
    const float* n1b    = (const float*)d_in[2];
    const float* qkvw   = (const float*)d_in[3];
    const float* qkvb   = (const float*)d_in[4];
    const float* projw  = (const float*)d_in[5];
    const float* projb  = (const float*)d_in[6];
    const float* ls1    = (const float*)d_in[7];
    const float* n2g    = (const float*)d_in[8];
    const float* n2b    = (const float*)d_in[9];
    const float* fc1w   = (const float*)d_in[10];
    const float* fc1b   = (const float*)d_in[11];
    const float* fc2w   = (const float*)d_in[12];
    const float* fc2b   = (const float*)d_in[13];
    const float* ls2    = (const float*)d_in[14];
    float* out = (float*)d_out;

    __nv_bfloat16 *xnorm, *qkv, *attn, *mlp, *qkvw_bf, *projw_bf, *fc1w_bf, *fc2w_bf;
    cudaGetSymbolAddress((void**)&xnorm,    g_xnorm);
    cudaGetSymbolAddress((void**)&qkv,      g_qkv);
    cudaGetSymbolAddress((void**)&attn,     g_attn);
    cudaGetSymbolAddress((void**)&mlp,      g_mlp);
    cudaGetSymbolAddress((void**)&qkvw_bf,  g_qkvw);
    cudaGetSymbolAddress((void**)&projw_bf, g_projw);
    cudaGetSymbolAddress((void**)&fc1w_bf,  g_fc1w);
    cudaGetSymbolAddress((void**)&fc2w_bf,  g_fc2w);

    cudaFuncSetAttribute(gemm_bf16<1>, cudaFuncAttributeMaxDynamicSharedMemorySize, GSM_BYTES);
    cudaFuncSetAttribute(gemm_bf16<2>, cudaFuncAttributeMaxDynamicSharedMemorySize, GSM_BYTES);
    cudaFuncSetAttribute(gemm_bf16<3>, cudaFuncAttributeMaxDynamicSharedMemorySize, GSM_BYTES);

    const int MT = (M_TOK + 127) / 128;  // 129
    const int QT = (SEQ + 127) / 128;    // 9

    // 0. weight conversion fp32 -> bf16 (single launch)
    f2bf_all_k<<<(N4_TOT + 255) / 256, 256>>>(qkvw, projw, fc1w, fc2w,
                                              qkvw_bf, projw_bf, fc1w_bf, fc2w_bf);

    // 1. LN1 -> bf16
    layernorm_k<<<M_TOK, 256>>>(hidden, n1g, n1b, xnorm);
    // 2. QKV -> bf16 (q columns pre-scaled by 0.125)
    gemm_bf16<1><<<dim3(3 * HID / 128, MT), 256, GSM_BYTES>>>(
        xnorm, qkvw_bf, qkvb, nullptr, nullptr, nullptr, qkv,
        M_TOK, 3 * HID, HID, HID);
    // 3-5. fused attention
    flash_attn<<<dim3(QT, BATCH * NHEADS), 256>>>(qkv, attn);
    // 6. proj + ls1 residual -> d_out (fp32)
    gemm_bf16<3><<<dim3(HID / 128, MT), 256, GSM_BYTES>>>(
        attn, projw_bf, projb, ls1, hidden, out, nullptr, M_TOK, HID, HID, 0);
    // 7. LN2 -> bf16
    layernorm_k<<<M_TOK, 256>>>(out, n2g, n2b, xnorm);
    // 8. fc1 + gelu -> bf16
    gemm_bf16<2><<<dim3(IMED / 128, MT), 256, GSM_BYTES>>>(
        xnorm, fc1w_bf, fc1b, nullptr, nullptr, nullptr, mlp,
        M_TOK, IMED, HID, 0);
    // 9. fc2 + ls2 residual -> d_out (fp32, in place)
    gemm_bf16<3><<<dim3(HID / 128, MT), 256, GSM_BYTES>>>(
        mlp, fc2w_bf, fc2b, ls2, out, out, nullptr, M_TOK, HID, IMED, 0);
}

// round 17
// speedup vs baseline: 1.2430x; 1.0169x over previous
#include <cuda_runtime.h>
#include <cuda_bf16.h>
#include <math.h>

// ---------------------------------------------------------------------------
// InternVisionLayer: B=16, S=1025, H=1024, NH=16, HD=64, I=4096, M = 16400
// R16: (a) flash q-tile 128->64, 4-warp CTAs, 4 CTAs/SM (4 independent
//      barrier domains; per-thread state unchanged, regs still 128);
//      (b) LN1 + weight f2bf merged into one prologue kernel.
//      Dense GEMMs identical to R15.
// ---------------------------------------------------------------------------

#define M_TOK   16400
#define SEQ     1025
#define BATCH   16
#define HID     1024
#define NHEADS  16
#define HDIM    64
#define IMED    4096

__device__ __nv_bfloat16 g_xnorm [(size_t)M_TOK * HID];
__device__ __nv_bfloat16 g_qkv   [(size_t)M_TOK * 3 * HID];
__device__ __nv_bfloat16 g_attn  [(size_t)M_TOK * HID];
__device__ __nv_bfloat16 g_mlp   [(size_t)M_TOK * IMED];
__device__ __nv_bfloat16 g_qkvw  [(size_t)3 * HID * HID];
__device__ __nv_bfloat16 g_projw [(size_t)HID * HID];
__device__ __nv_bfloat16 g_fc1w  [(size_t)IMED * HID];
__device__ __nv_bfloat16 g_fc2w  [(size_t)HID * IMED];

// ---------------------------------------------------------------------------
// helpers
// ---------------------------------------------------------------------------
__device__ __forceinline__ void mma_bf16(float* d, const unsigned* a, const unsigned* b) {
    asm volatile(
        "mma.sync.aligned.m16n8k16.row.col.f32.bf16.bf16.f32 "
        "{%0,%1,%2,%3}, {%4,%5,%6,%7}, {%8,%9}, {%0,%1,%2,%3};"
        : "+f"(d[0]), "+f"(d[1]), "+f"(d[2]), "+f"(d[3])
        : "r"(a[0]), "r"(a[1]), "r"(a[2]), "r"(a[3]), "r"(b[0]), "r"(b[1]));
}

__device__ __forceinline__ void ldm_x4(unsigned& r0, unsigned& r1, unsigned& r2,
                                       unsigned& r3, unsigned saddr) {
    asm volatile("ldmatrix.sync.aligned.m8n8.x4.shared.b16 {%0,%1,%2,%3}, [%4];"
                 : "=r"(r0), "=r"(r1), "=r"(r2), "=r"(r3) : "r"(saddr));
}
__device__ __forceinline__ void ldm_x4t(unsigned& r0, unsigned& r1, unsigned& r2,
                                        unsigned& r3, unsigned saddr) {
    asm volatile("ldmatrix.sync.aligned.m8n8.x4.trans.shared.b16 {%0,%1,%2,%3}, [%4];"
                 : "=r"(r0), "=r"(r1), "=r"(r2), "=r"(r3) : "r"(saddr));
}

__device__ __forceinline__ void cp16s(unsigned sa, const void* gsrc) {
    asm volatile("cp.async.cg.shared.global [%0], [%1], 16;\n"
                 :: "r"(sa), "l"(gsrc));
}
__device__ __forceinline__ void cp_commit() { asm volatile("cp.async.commit_group;"); }

__device__ __forceinline__ float gelu_f(float v) {
    return 0.5f * v * (1.0f + erff(v * 0.70710678118654752f));
}

__device__ __forceinline__ unsigned packbf2(float lo, float hi) {
    __nv_bfloat162 p = __floats2bfloat162_rn(lo, hi);
    return *(unsigned*)&p;
}

// 128-byte rows, 8 x 16B chunks, XOR swizzle (conflict-free for ldmatrix)
__device__ __forceinline__ unsigned swz128(int r, int c) {
    return (unsigned)(r * 128 + (((c ^ r) & 7) << 4));
}

// ---------------------------------------------------------------------------
// Prologue: LN1 (blocks [0, M_TOK)) + weight fp32->bf16 (remaining blocks).
// ---------------------------------------------------------------------------
#define N4_QKVW (3 * HID * HID / 4)
#define N4_PROJ (HID * HID / 4)
#define N4_FC1  (IMED * HID / 4)
#define N4_FC2  (HID * IMED / 4)
#define N4_TOT  (N4_QKVW + N4_PROJ + N4_FC1 + N4_FC2)
#define CONV_BLOCKS ((N4_TOT + 255) / 256)

__global__ void prologue_k(const float* __restrict__ hidden,
                           const float* __restrict__ n1g,
                           const float* __restrict__ n1b,
                           __nv_bfloat16* __restrict__ xnorm,
                           const float* __restrict__ qkvw,
                           const float* __restrict__ projw,
                           const float* __restrict__ fc1w,
                           const float* __restrict__ fc2w,
                           __nv_bfloat16* __restrict__ o_qkvw,
                           __nv_bfloat16* __restrict__ o_projw,
                           __nv_bfloat16* __restrict__ o_fc1w,
                           __nv_bfloat16* __restrict__ o_fc2w) {
    int t = threadIdx.x;
    if (blockIdx.x < M_TOK) {
        // ---- LayerNorm row ----
        int row = blockIdx.x;
        const float4* xr = (const float4*)(hidden + (size_t)row * HID);
        float4 v = xr[t];
        float s  = v.x + v.y + v.z + v.w;
        float ss = v.x*v.x + v.y*v.y + v.z*v.z + v.w*v.w;
        #pragma unroll
        for (int o = 16; o; o >>= 1) {
            s  += __shfl_xor_sync(0xffffffffu, s,  o);
            ss += __shfl_xor_sync(0xffffffffu, ss, o);
        }
        __shared__ float sh[16];
        if ((t & 31) == 0) { sh[t >> 5] = s; sh[8 + (t >> 5)] = ss; }
        __syncthreads();
        s = 0.f; ss = 0.f;
        #pragma unroll
        for (int i = 0; i < 8; i++) { s += sh[i]; ss += sh[8 + i]; }
        float mean = s * (1.0f / HID);
        float var  = ss * (1.0f / HID) - mean * mean;
        float inv  = rsqrtf(var + 1e-5f);
        float4 gv = ((const float4*)n1g)[t];
        float4 bv = ((const float4*)n1b)[t];
        __nv_bfloat162* orow = (__nv_bfloat162*)(xnorm + (size_t)row * HID);
        orow[2 * t + 0] = __floats2bfloat162_rn((v.x - mean) * inv * gv.x + bv.x,
                                                (v.y - mean) * inv * gv.y + bv.y);
        orow[2 * t + 1] = __floats2bfloat162_rn((v.z - mean) * inv * gv.z + bv.z,
                                                (v.w - mean) * inv * gv.w + bv.w);
    } else {
        // ---- weight conversion segment ----
        int i = (blockIdx.x - M_TOK) * 256 + t;
        if (i >= N4_TOT) return;
        const float* in;
        __nv_bfloat16* out;
        if (i < N4_QKVW) {
            in = qkvw; out = o_qkvw;
        } else if (i < N4_QKVW + N4_PROJ) {
            i -= N4_QKVW; in = projw; out = o_projw;
        } else if (i < N4_QKVW + N4_PROJ + N4_FC1) {
            i -= N4_QKVW + N4_PROJ; in = fc1w; out = o_fc1w;
        } else {
            i -= N4_QKVW + N4_PROJ + N4_FC1; in = fc2w; out = o_fc2w;
        }
        float4 v = ((const float4*)in)[i];
        ((__nv_bfloat162*)out)[2 * i + 0] = __floats2bfloat162_rn(v.x, v.y);
        ((__nv_bfloat162*)out)[2 * i + 1] = __floats2bfloat162_rn(v.z, v.w);
    }
}

// ---------------------------------------------------------------------------
// LayerNorm (LN2): one block per row; bf16 output
// ---------------------------------------------------------------------------
__global__ void layernorm_k(const float* __restrict__ x,
                            const float* __restrict__ g,
                            const float* __restrict__ b,
                            __nv_bfloat16* __restrict__ out) {
    int row = blockIdx.x;
    int t = threadIdx.x;
    const float4* xr = (const float4*)(x + (size_t)row * HID);
    float4 v = xr[t];
    float s  = v.x + v.y + v.z + v.w;
    float ss = v.x*v.x + v.y*v.y + v.z*v.z + v.w*v.w;
    #pragma unroll
    for (int o = 16; o; o >>= 1) {
        s  += __shfl_xor_sync(0xffffffffu, s,  o);
        ss += __shfl_xor_sync(0xffffffffu, ss, o);
    }
    __shared__ float sh[16];
    if ((t & 31) == 0) { sh[t >> 5] = s; sh[8 + (t >> 5)] = ss; }
    __syncthreads();
    s = 0.f; ss = 0.f;
    #pragma unroll
    for (int i = 0; i < 8; i++) { s += sh[i]; ss += sh[8 + i]; }
    float mean = s * (1.0f / HID);
    float var  = ss * (1.0f / HID) - mean * mean;
    float inv  = rsqrtf(var + 1e-5f);
    float4 gv = ((const float4*)g)[t];
    float4 bv = ((const float4*)b)[t];
    __nv_bfloat162* orow = (__nv_bfloat162*)(out + (size_t)row * HID);
    orow[2 * t + 0] = __floats2bfloat162_rn((v.x - mean) * inv * gv.x + bv.x,
                                            (v.y - mean) * inv * gv.y + bv.y);
    orow[2 * t + 1] = __floats2bfloat162_rn((v.z - mean) * inv * gv.z + bv.z,
                                            (v.w - mean) * inv * gv.w + bv.w);
}

// ---------------------------------------------------------------------------
// bf16 MMA GEMM: C = A[M,K] * B[N,K]^T, CTA 128x128, 8 warps of 64x32.
// K-chunk 64 (128B rows, swz128), 3-stage cp.async ring, ONE barrier/chunk.
// MODE 1: (v+bias)*blk_scale -> bf16   (blk_scale = 0.125 for q-tiles of QKV)
// MODE 2: +bias, gelu -> bf16
// MODE 3: resid + ls*( . + bias ) -> fp32
// ---------------------------------------------------------------------------
#define GSM_STAGE 32768
#define GSM_BYTES (3 * GSM_STAGE)

template <int MODE>
__global__ void __launch_bounds__(256, 2)
gemm_bf16(const __nv_bfloat16* __restrict__ A, const __nv_bfloat16* __restrict__ Bw,
          const float* __restrict__ bias, const float* __restrict__ ls,
          const float* __restrict__ resid, float* __restrict__ Cf,
          __nv_bfloat16* __restrict__ Cb, int M, int N, int K, int qcut) {
    extern __shared__ __align__(128) char smx[];

    const int t  = threadIdx.x;
    const int w  = t >> 5;
    const int lane = t & 31;
    const int g  = lane >> 2;
    const int t4 = lane & 3;
    const int wm = (w >> 2) * 64;
    const int wn = (w & 3) * 32;
    const int m0 = blockIdx.y * 128;
    const int n0 = blockIdx.x * 128;

    const unsigned smb = (unsigned)__cvta_generic_to_shared(smx);

    const float blk_scale = (MODE == 1 && n0 < qcut) ? 0.125f : 1.0f;

    float d[4][4][4];
    #pragma unroll
    for (int i = 0; i < 4; i++)
        #pragma unroll
        for (int j = 0; j < 4; j++)
            #pragma unroll
            for (int r = 0; r < 4; r++) d[i][j][r] = 0.f;

    auto stage = [&](int sg, int k0) {
        unsigned ab = smb + sg * GSM_STAGE;
        unsigned bb = ab + 16384;
        #pragma unroll
        for (int i = 0; i < 4; i++) {
            int id = t + i * 256;
            int r = id >> 3, c = id & 7;
            int rm = min(m0 + r, M - 1);
            cp16s(ab + swz128(r, c), A  + (size_t)rm * K + k0 + c * 8);
            cp16s(bb + swz128(r, c), Bw + (size_t)(n0 + r) * K + k0 + c * 8);
        }
    };

    const int a_row = (lane & 15);
    const int a_c   = (lane >> 4);
    const int b_row = ((lane >> 4) << 3) + (lane & 7);
    const int b_c   = ((lane >> 3) & 1);

    const int NC = K >> 6;
    stage(0, 0);  cp_commit();
    stage(1, 64); cp_commit();

    int cs = 0, ss = 2;
    for (int kc = 0; kc < NC; kc++) {
        asm volatile("cp.async.wait_group 1;");
        __syncthreads();

        if (kc + 2 < NC) stage(ss, (kc + 2) << 6);
        cp_commit();

        const unsigned ab = smb + cs * GSM_STAGE;
        const unsigned bb = ab + 16384;
        #pragma unroll
        for (int s = 0; s < 4; s++) {
            unsigned af[4][4], bf[2][4];
            #pragma unroll
            for (int i = 0; i < 4; i++)
                ldm_x4(af[i][0], af[i][1], af[i][2], af[i][3],
                       ab + swz128(wm + i * 16 + a_row, 2 * s + a_c));
            #pragma unroll
            for (int jj = 0; jj < 2; jj++)
                ldm_x4(bf[jj][0], bf[jj][1], bf[jj][2], bf[jj][3],
                       bb + swz128(wn + jj * 16 + b_row, 2 * s + b_c));
            #pragma unroll
            for (int i = 0; i < 4; i++)
                #pragma unroll
                for (int j = 0; j < 4; j++)
                    mma_bf16(d[i][j], af[i], &bf[j >> 1][(j & 1) * 2]);
        }
        cs = (cs == 2) ? 0 : cs + 1;
        ss = (ss == 2) ? 0 : ss + 1;
    }

    #pragma unroll
    for (int i = 0; i < 4; i++) {
        int rbase = m0 + wm + i * 16 + g;
        #pragma unroll
        for (int rr = 0; rr < 2; rr++) {
            int row = rbase + 8 * rr;
            if (row >= M) continue;
            #pragma unroll
            for (int j = 0; j < 4; j++) {
                int col = n0 + wn + j * 8 + 2 * t4;
                float v0 = d[i][j][rr * 2 + 0];
                float v1 = d[i][j][rr * 2 + 1];
                size_t idx = (size_t)row * N + col;
                if (MODE == 1) {
                    v0 = (v0 + bias[col])     * blk_scale;
                    v1 = (v1 + bias[col + 1]) * blk_scale;
                    *(__nv_bfloat162*)(Cb + idx) = __floats2bfloat162_rn(v0, v1);
                } else if (MODE == 2) {
                    v0 = gelu_f(v0 + bias[col]);
                    v1 = gelu_f(v1 + bias[col + 1]);
                    *(__nv_bfloat162*)(Cb + idx) = __floats2bfloat162_rn(v0, v1);
                } else {
                    float2 rv = *(const float2*)(resid + idx);
                    v0 = rv.x + ls[col]     * (v0 + bias[col]);
                    v1 = rv.y + ls[col + 1] * (v1 + bias[col + 1]);
                    *(float2*)(Cf + idx) = make_float2(v0, v1);
                }
            }
        }
    }
}

// ---------------------------------------------------------------------------
// bf16 flash attention. CTA = (q-tile 64, b*h), 4 warps x 16 q rows.
// 4 CTAs/SM -> 4 independent barrier domains. Q pre-scaled by 0.125.
// SMEM (static 40KB): Q 64x128B | K 2x64x128B | V 2x64x128B
// ---------------------------------------------------------------------------
#define NIT 17

__global__ void __launch_bounds__(128, 4)
flash_attn(const __nv_bfloat16* __restrict__ qkv, __nv_bfloat16* __restrict__ out) {
    __shared__ __align__(128) char sm[40960];
    const unsigned smb = (unsigned)__cvta_generic_to_shared(sm);
    const unsigned smK = smb + 8192;
    const unsigned smV = smb + 24576;

    const int t  = threadIdx.x;
    const int w  = t >> 5;
    const int lane = t & 31;
    const int g  = lane >> 2;
    const int t4 = lane & 3;
    const int q0 = blockIdx.x * 64;
    const int z  = blockIdx.y, b = z >> 4, h = z & 15;

    const __nv_bfloat16* Qg = qkv + (size_t)b * SEQ * (3 * HID) + h * HDIM;
    const __nv_bfloat16* Kg = Qg + HID;
    const __nv_bfloat16* Vg = Qg + 2 * HID;

    // ---- stage Q (64 rows x 8 chunks) + KV tile 0 (64 x 8 each) ----
    {
        #pragma unroll
        for (int i = 0; i < 4; i++) {
            int id = t + i * 128;
            int r = id >> 3, c = id & 7;
            int row = min(q0 + r, SEQ - 1);
            cp16s(smb + swz128(r, c), Qg + (size_t)row * (3 * HID) + c * 8);
        }
        #pragma unroll
        for (int i = 0; i < 4; i++) {
            int id = t + i * 128;
            int r = id >> 3, c = id & 7;
            cp16s(smK + swz128(r, c), Kg + (size_t)r * (3 * HID) + c * 8);
            cp16s(smV + swz128(r, c), Vg + (size_t)r * (3 * HID) + c * 8);
        }
        cp_commit();
        asm volatile("cp.async.wait_group 0;");
        __syncthreads();
    }

    unsigned qf[4][4];
    #pragma unroll
    for (int kc = 0; kc < 4; kc++)
        ldm_x4(qf[kc][0], qf[kc][1], qf[kc][2], qf[kc][3],
               smb + swz128(w * 16 + (lane & 15), kc * 2 + (lane >> 4)));

    float m0 = -1e30f, m1 = -1e30f;
    float lp0 = 0.f, lp1 = 0.f;   // quad-partial l accumulators
    float o[8][4];
    #pragma unroll
    for (int j = 0; j < 8; j++)
        #pragma unroll
        for (int r = 0; r < 4; r++) o[j][r] = 0.f;

    const int nt_r = (lane & 7);
    const int nt_p = (lane >> 4);
    const int nt_k = ((lane >> 3) & 1);

    for (int it = 0; it < NIT; it++) {
        const int buf = it & 1;
        const int kv0 = it * 64;

        if (it + 1 < NIT) {
            int nb = buf ^ 1;
            #pragma unroll
            for (int i = 0; i < 4; i++) {
                int id = t + i * 128;
                int r = id >> 3, c = id & 7;
                int row = min(kv0 + 64 + r, SEQ - 1);
                cp16s(smK + nb * 8192 + swz128(r, c), Kg + (size_t)row * (3 * HID) + c * 8);
                cp16s(smV + nb * 8192 + swz128(r, c), Vg + (size_t)row * (3 * HID) + c * 8);
            }
            cp_commit();
        }

        // ---- S = (Q*0.125) K^T ----
        const unsigned kb = smK + buf * 8192;
        float s[8][4];
        #pragma unroll
        for (int j = 0; j < 8; j++)
            #pragma unroll
            for (int r = 0; r < 4; r++) s[j][r] = 0.f;
        #pragma unroll
        for (int kc = 0; kc < 4; kc++) {
            #pragma unroll
            for (int jp = 0; jp < 4; jp++) {
                unsigned kf[4];
                ldm_x4(kf[0], kf[1], kf[2], kf[3],
                       kb + swz128((2 * jp + nt_p) * 8 + nt_r, kc * 2 + nt_k));
                mma_bf16(s[2 * jp],     qf[kc], kf);
                mma_bf16(s[2 * jp + 1], qf[kc], kf + 2);
            }
        }

        // ---- tail mask (last tile only) ----
        const int lim = SEQ - kv0;
        if (lim < 64) {
            #pragma unroll
            for (int j = 0; j < 8; j++) {
                int cc = j * 8 + 2 * t4;
                if (cc     >= lim) { s[j][0] = -1e30f; s[j][2] = -1e30f; }
                if (cc + 1 >= lim) { s[j][1] = -1e30f; s[j][3] = -1e30f; }
            }
        }

        // ---- online max (quad reduction) ----
        float mx0 = -1e30f, mx1 = -1e30f;
        #pragma unroll
        for (int j = 0; j < 8; j++) {
            mx0 = fmaxf(mx0, fmaxf(s[j][0], s[j][1]));
            mx1 = fmaxf(mx1, fmaxf(s[j][2], s[j][3]));
        }
        mx0 = fmaxf(mx0, __shfl_xor_sync(0xffffffffu, mx0, 1));
        mx0 = fmaxf(mx0, __shfl_xor_sync(0xffffffffu, mx0, 2));
        mx1 = fmaxf(mx1, __shfl_xor_sync(0xffffffffu, mx1, 1));
        mx1 = fmaxf(mx1, __shfl_xor_sync(0xffffffffu, mx1, 2));

        float mn0 = fmaxf(m0, mx0), mn1 = fmaxf(m1, mx1);
        float a0 = __expf(m0 - mn0), a1 = __expf(m1 - mn1);
        m0 = mn0; m1 = mn1;

        // ---- fused exp + quad-partial sum + pack ----
        unsigned pa[4][4];
        float rs0 = 0.f, rs1 = 0.f;
        #pragma unroll
        for (int kk = 0; kk < 4; kk++) {
            float e00 = __expf(s[2 * kk][0] - m0);
            float e01 = __expf(s[2 * kk][1] - m0);
            float e02 = __expf(s[2 * kk][2] - m1);
            float e03 = __expf(s[2 * kk][3] - m1);
            rs0 += e00 + e01;
            rs1 += e02 + e03;
            pa[kk][0] = packbf2(e00, e01);
            pa[kk][1] = packbf2(e02, e03);
            float e10 = __expf(s[2 * kk + 1][0] - m0);
            float e11 = __expf(s[2 * kk + 1][1] - m0);
            float e12 = __expf(s[2 * kk + 1][2] - m1);
            float e13 = __expf(s[2 * kk + 1][3] - m1);
            rs0 += e10 + e11;
            rs1 += e12 + e13;
            pa[kk][2] = packbf2(e10, e11);
            pa[kk][3] = packbf2(e12, e13);
        }
        lp0 = lp0 * a0 + rs0;
        lp1 = lp1 * a1 + rs1;

        // ---- rescale O ----
        #pragma unroll
        for (int j = 0; j < 8; j++) {
            o[j][0] *= a0; o[j][1] *= a0; o[j][2] *= a1; o[j][3] *= a1;
        }

        // ---- O += P V ----
        const unsigned vb = smV + buf * 8192;
        #pragma unroll
        for (int kk = 0; kk < 4; kk++) {
            #pragma unroll
            for (int jp = 0; jp < 4; jp++) {
                unsigned vf[4];
                ldm_x4t(vf[0], vf[1], vf[2], vf[3],
                        vb + swz128(kk * 16 + nt_k * 8 + nt_r, 2 * jp + nt_p));
                mma_bf16(o[2 * jp],     pa[kk], vf);
                mma_bf16(o[2 * jp + 1], pa[kk], vf + 2);
            }
        }

        if (it + 1 < NIT) {
            asm volatile("cp.async.wait_group 0;");
            __syncthreads();
        }
    }

    // ---- deferred l reduction (quad sum, once) ----
    float l0 = lp0, l1 = lp1;
    l0 += __shfl_xor_sync(0xffffffffu, l0, 1);
    l0 += __shfl_xor_sync(0xffffffffu, l0, 2);
    l1 += __shfl_xor_sync(0xffffffffu, l1, 1);
    l1 += __shfl_xor_sync(0xffffffffu, l1, 2);

    float inv0 = 1.f / l0, inv1 = 1.f / l1;
    int row0 = q0 + w * 16 + g;
    int row1 = row0 + 8;
    #pragma unroll
    for (int j = 0; j < 8; j++) {
        int col = j * 8 + 2 * t4;
        if (row0 < SEQ)
            *(__nv_bfloat162*)(out + ((size_t)b * SEQ + row0) * HID + h * HDIM + col) =
                __floats2bfloat162_rn(o[j][0] * inv0, o[j][1] * inv0);
        if (row1 < SEQ)
            *(__nv_bfloat162*)(out + ((size_t)b * SEQ + row1) * HID + h * HDIM + col) =
                __floats2bfloat162_rn(o[j][2] * inv1, o[j][3] * inv1);
    }
}

// ---------------------------------------------------------------------------
extern "C" void kernel_launch(void* const* d_in, const int* in_sizes, int n_in,
                              void* d_out, int out_size) {
    const float* hidden = (const float*)d_in[0];
    const float* n1g    = (const float*)d_in[1];
    const float* n1b    = (const float*)d_in[2];
    const float* qkvw   = (const float*)d_in[3];
    const float* qkvb   = (const float*)d_in[4];
    const float* projw  = (const float*)d_in[5];
    const float* projb  = (const float*)d_in[6];
    const float* ls1    = (const float*)d_in[7];
    const float* n2g    = (const float*)d_in[8];
    const float* n2b    = (const float*)d_in[9];
    const float* fc1w   = (const float*)d_in[10];
    const float* fc1b   = (const float*)d_in[11];
    const float* fc2w   = (const float*)d_in[12];
    const float* fc2b   = (const float*)d_in[13];
    const float* ls2    = (const float*)d_in[14];
    float* out = (float*)d_out;

    __nv_bfloat16 *xnorm, *qkv, *attn, *mlp, *qkvw_bf, *projw_bf, *fc1w_bf, *fc2w_bf;
    cudaGetSymbolAddress((void**)&xnorm,    g_xnorm);
    cudaGetSymbolAddress((void**)&qkv,      g_qkv);
    cudaGetSymbolAddress((void**)&attn,     g_attn);
    cudaGetSymbolAddress((void**)&mlp,      g_mlp);
    cudaGetSymbolAddress((void**)&qkvw_bf,  g_qkvw);
    cudaGetSymbolAddress((void**)&projw_bf, g_projw);
    cudaGetSymbolAddress((void**)&fc1w_bf,  g_fc1w);
    cudaGetSymbolAddress((void**)&fc2w_bf,  g_fc2w);

    cudaFuncSetAttribute(gemm_bf16<1>, cudaFuncAttributeMaxDynamicSharedMemorySize, GSM_BYTES);
    cudaFuncSetAttribute(gemm_bf16<2>, cudaFuncAttributeMaxDynamicSharedMemorySize, GSM_BYTES);
    cudaFuncSetAttribute(gemm_bf16<3>, cudaFuncAttributeMaxDynamicSharedMemorySize, GSM_BYTES);

    const int MT = (M_TOK + 127) / 128;  // 129
    const int QT = (SEQ + 63) / 64;      // 17

    // 0+1. prologue: LN1 + weight conversion (one launch)
    prologue_k<<<M_TOK + CONV_BLOCKS, 256>>>(hidden, n1g, n1b, xnorm,
                                             qkvw, projw, fc1w, fc2w,
                                             qkvw_bf, projw_bf, fc1w_bf, fc2w_bf);
    // 2. QKV -> bf16 (q columns pre-scaled by 0.125)
    gemm_bf16<1><<<dim3(3 * HID / 128, MT), 256, GSM_BYTES>>>(
        xnorm, qkvw_bf, qkvb, nullptr, nullptr, nullptr, qkv,
        M_TOK, 3 * HID, HID, HID);
    // 3-5. fused attention (q-tile 64, 4 warps)
    flash_attn<<<dim3(QT, BATCH * NHEADS), 128>>>(qkv, attn);
    // 6. proj + ls1 residual -> d_out (fp32)
    gemm_bf16<3><<<dim3(HID / 128, MT), 256, GSM_BYTES>>>(
        attn, projw_bf, projb, ls1, hidden, out, nullptr, M_TOK, HID, HID, 0);
    // 7. LN2 -> bf16
    layernorm_k<<<M_TOK, 256>>>(out, n2g, n2b, xnorm);
    // 8. fc1 + gelu -> bf16
    gemm_bf16<2><<<dim3(IMED / 128, MT), 256, GSM_BYTES>>>(
        xnorm, fc1w_bf, fc1b, nullptr, nullptr, nullptr, mlp,
        M_TOK, IMED, HID, 0);
    // 9. fc2 + ls2 residual -> d_out (fp32, in place)
    gemm_bf16<3><<<dim3(HID / 128, MT), 256, GSM_BYTES>>>(
        mlp, fc2w_bf, fc2b, ls2, out, out, nullptr, M_TOK, HID, IMED, 0);
}